// round 6
// baseline (speedup 1.0000x reference)
#include <cuda_runtime.h>
#include <math.h>
#include <stdint.h>

// Problem constants
#define BB   2
#define TT   512
#define DM   1024
#define DH   4096
#define DD   4
#define VV   32000
#define ROWS (BB*TT*DD)   // 4096
#define BTN  (BB*TT)      // 1024
#define SPLITK 4

// Scratch (static device globals — no allocation allowed)
__device__ float  g_Shi [ROWS*DM];
__device__ float  g_Slo [ROWS*DM];
__device__ float  g_Ghi [ROWS*DH];
__device__ float  g_Glo [ROWS*DH];
__device__ float  g_W1thi[DH*DM];
__device__ float  g_W1tlo[DH*DM];
__device__ float  g_W2thi[DM*DH];
__device__ float  g_W2tlo[DM*DH];
__device__ float  g_P  [SPLITK*ROWS*DM];  // split-K partials for S2
__device__ float  g_S2 [ROWS*DM];     // exact fp32 S2 (compacted rows)
__device__ float  g_S2r[ROWS*DM];     // tf32-rounded S2 (compacted rows)
__device__ float  g_Wt [VV*DM];       // transposed+rounded Wq
__device__ float  g_beta[ROWS];       // orig indexing
__device__ int    g_idx [BTN];        // compacted bt index map
__device__ int    g_cnt [1];          // nv4 = 4 * (#valid bt)
__device__ double g_acc[4];

// ============================================================================
__device__ __forceinline__ uint32_t smem_u32(const void* p) {
    uint32_t a;
    asm("{ .reg .u64 t; cvta.to.shared.u64 t, %1; cvt.u32.u64 %0, t; }"
        : "=r"(a) : "l"(p));
    return a;
}
__device__ __forceinline__ float rna_tf32(float v) {
    uint32_t r;
    asm("cvt.rna.tf32.f32 %0, %1;" : "=r"(r) : "f"(v));
    return __uint_as_float(r);
}
__device__ __forceinline__ void cp16(uint32_t s, const void* g) {
    asm volatile("cp.async.cg.shared.global [%0], [%1], 16;" :: "r"(s), "l"(g));
}
#define CP_COMMIT() asm volatile("cp.async.commit_group;" ::: "memory")
#define CP_WAIT0()  asm volatile("cp.async.wait_group 0;" ::: "memory")

__device__ __forceinline__ void mma_tf32_16x8x8(float* d, const uint32_t* a,
                                                const uint32_t* b) {
    asm volatile(
        "mma.sync.aligned.m16n8k8.row.col.f32.tf32.tf32.f32 "
        "{%0,%1,%2,%3}, {%4,%5,%6,%7}, {%8,%9}, {%0,%1,%2,%3};"
        : "+f"(d[0]), "+f"(d[1]), "+f"(d[2]), "+f"(d[3])
        : "r"(a[0]), "r"(a[1]), "r"(a[2]), "r"(a[3]), "r"(b[0]), "r"(b[1]));
}

// ============================================================================
__global__ void zero_acc_kernel() {
    if (threadIdx.x < 4) g_acc[threadIdx.x] = 0.0;
}

// ---------------------------------------------------------------------------
__global__ void compact_kernel(const int* __restrict__ mask) {
    __shared__ int pre[BTN];
    int tid = threadIdx.x;
    int m = (mask[tid] != 0) ? 1 : 0;
    pre[tid] = m;
    __syncthreads();
    for (int o = 1; o < BTN; o <<= 1) {
        int v = (tid >= o) ? pre[tid - o] : 0;
        __syncthreads();
        pre[tid] += v;
        __syncthreads();
    }
    int mv = pre[BTN - 1];
    if (m) g_idx[pre[tid] - 1] = tid;
    if (tid >= mv) g_idx[tid] = 0;
    if (tid == 0) g_cnt[0] = mv * 4;
}

// ---------------------------------------------------------------------------
__global__ void zero_fill_kernel(const int* __restrict__ mask,
                                 float* __restrict__ q,
                                 float* __restrict__ obeta,
                                 float* __restrict__ ok)
{
    int bt = blockIdx.x;
    if (mask[bt] != 0) return;
    int tid = threadIdx.x;
    float4* dst = (float4*)(q + (size_t)bt * 4 * VV);
#pragma unroll 4
    for (int i = tid; i < 32000; i += 256) dst[i] = make_float4(0.f, 0.f, 0.f, 0.f);
    if (tid < 4) {
        obeta[bt * 4 + tid] = 0.f;
        ok[bt * 4 + tid]    = 0.f;
    }
}

// ---------------------------------------------------------------------------
__global__ void s_kernel(const float* __restrict__ H, const int* __restrict__ ids,
                         const float* __restrict__ emb, const float* __restrict__ demb,
                         const float* __restrict__ lng, const float* __restrict__ lnb)
{
    int rp = blockIdx.x;
    if (rp >= g_cnt[0]) return;
    int bt  = g_idx[rp >> 2];
    int d   = rp & 3;
    int tid = threadIdx.x;

    const float* hrow = H    + (size_t)bt * DM;
    const float* erow = emb  + (size_t)ids[bt] * DM;
    const float* drow = demb + (size_t)d * DM;

    float x[4];
    float s = 0.f;
#pragma unroll
    for (int j = 0; j < 4; j++) {
        int i = j * 256 + tid;
        x[j] = hrow[i] + erow[i] + drow[i];
        s += x[j];
    }
    __shared__ float red[256];
    red[tid] = s; __syncthreads();
    for (int o = 128; o > 0; o >>= 1) { if (tid < o) red[tid] += red[tid + o]; __syncthreads(); }
    float mu = red[0] * (1.0f / DM);
    __syncthreads();

    float v = 0.f;
#pragma unroll
    for (int j = 0; j < 4; j++) { float dx = x[j] - mu; v += dx * dx; }
    red[tid] = v; __syncthreads();
    for (int o = 128; o > 0; o >>= 1) { if (tid < o) red[tid] += red[tid + o]; __syncthreads(); }
    float inv = rsqrtf(red[0] * (1.0f / DM) + 1e-5f);

#pragma unroll
    for (int j = 0; j < 4; j++) {
        int i = j * 256 + tid;
        float val = (x[j] - mu) * inv * lng[i] + lnb[i];
        float hi  = rna_tf32(val);
        g_Shi[(size_t)rp * DM + i] = hi;
        g_Slo[(size_t)rp * DM + i] = rna_tf32(val - hi);
    }
}

// ---------------------------------------------------------------------------
__global__ void transpose_split_kernel(const float* __restrict__ W,
                                       float* __restrict__ Dhi, float* __restrict__ Dlo,
                                       int R, int C)
{
    __shared__ float tile[32][33];
    int bx = blockIdx.x;
    int by = blockIdx.y;
    int x  = threadIdx.x;
    int y0 = threadIdx.y;
#pragma unroll
    for (int yy = 0; yy < 32; yy += 8)
        tile[y0 + yy][x] = W[(size_t)(by * 32 + y0 + yy) * C + bx * 32 + x];
    __syncthreads();
#pragma unroll
    for (int yy = 0; yy < 32; yy += 8) {
        float v  = tile[x][y0 + yy];
        float hi = rna_tf32(v);
        size_t o = (size_t)(bx * 32 + y0 + yy) * R + by * 32 + x;
        Dhi[o] = hi;
        Dlo[o] = rna_tf32(v - hi);
    }
}

__global__ void transpose_round_kernel(const float* __restrict__ W) {
    __shared__ float tile[32][33];
    int bx = blockIdx.x;
    int by = blockIdx.y;
    int x  = threadIdx.x;
    int y0 = threadIdx.y;
#pragma unroll
    for (int yy = 0; yy < 32; yy += 8) {
        float v = W[(size_t)(by * 32 + y0 + yy) * VV + bx * 32 + x];
        tile[y0 + yy][x] = rna_tf32(v);
    }
    __syncthreads();
#pragma unroll
    for (int yy = 0; yy < 32; yy += 8)
        g_Wt[(size_t)(bx * 32 + y0 + yy) * DM + by * 32 + x] = tile[x][y0 + yy];
}

// ---------------------------------------------------------------------------
#define KCH    32
#define LSTR   36
#define TILE_F (128 * LSTR)

#define STG3_F (4 * TILE_F)
#define SM3_BYTES (2 * STG3_F * 4)

// 3xTF32 MLP GEMM on compacted rows
// MODE 0: O1/O2 = gelu hi/lo, full K
// MODE 2: split-K partial: blockIdx.z selects K chunk; raw acc -> O1 partials
template<int MODE>
__global__ void __launch_bounds__(256, 1)
mlp3_kernel(const float* __restrict__ Ahi, const float* __restrict__ Alo,
            const float* __restrict__ Bhi, const float* __restrict__ Blo,
            const float* __restrict__ bias,
            float* __restrict__ O1, float* __restrict__ O2,
            int N, int K)
{
    const int rowBase = blockIdx.x * 128;
    if (rowBase >= g_cnt[0]) return;
    extern __shared__ float smem[];
    const uint32_t su = smem_u32(smem);
    const int tid     = threadIdx.x;
    const int colBase = blockIdx.y * 128;

    int koff  = 0;
    int niter = K / KCH;
    if (MODE == 2) {
        koff  = blockIdx.z * (K / SPLITK);
        niter = K / SPLITK / KCH;
        O1   += (size_t)blockIdx.z * ROWS * DM;
    }

    const int lane = tid & 31, wid = tid >> 5;
    const int wr = wid >> 1, wc = wid & 1;
    const int g  = lane >> 2, tig = lane & 3;

    float acc[2][8][4];
#pragma unroll
    for (int mt = 0; mt < 2; mt++)
#pragma unroll
        for (int nt = 0; nt < 8; nt++)
#pragma unroll
            for (int k = 0; k < 4; k++) acc[mt][nt][k] = 0.f;

    const float* srcs[4] = {
        Ahi + (size_t)rowBase * K + koff, Alo + (size_t)rowBase * K + koff,
        Bhi + (size_t)colBase * K + koff, Blo + (size_t)colBase * K + koff };

    auto load_stage = [&](int s, int c) {
#pragma unroll
        for (int t = 0; t < 4; t++) {
            uint32_t base = su + (s * STG3_F + t * TILE_F) * 4;
            const float* gp = srcs[t] + c * KCH;
#pragma unroll
            for (int j = 0; j < 4; j++) {
                int idx = tid + 256 * j;
                int row = idx >> 3, seg = idx & 7;
                cp16(base + (row * LSTR + seg * 4) * 4,
                     gp + (size_t)row * K + seg * 4);
            }
        }
    };

    load_stage(0, 0);
    CP_COMMIT();

    for (int it = 0; it < niter; it++) {
        int s = it & 1;
        CP_WAIT0();
        __syncthreads();
        if (it + 1 < niter) { load_stage(1 - s, it + 1); CP_COMMIT(); }

        const float* Ah = smem + s * STG3_F;
        const float* Al = Ah + TILE_F;
        const float* Bh = Al + TILE_F;
        const float* Bl = Bh + TILE_F;

#pragma unroll
        for (int k8 = 0; k8 < 4; k8++) {
            int kb = k8 * 8;
            uint32_t ah[2][4], al[2][4];
#pragma unroll
            for (int mt = 0; mt < 2; mt++) {
                int m0 = wr * 32 + mt * 16;
                ah[mt][0] = __float_as_uint(Ah[(m0 + g    ) * LSTR + kb + tig    ]);
                ah[mt][1] = __float_as_uint(Ah[(m0 + g + 8) * LSTR + kb + tig    ]);
                ah[mt][2] = __float_as_uint(Ah[(m0 + g    ) * LSTR + kb + tig + 4]);
                ah[mt][3] = __float_as_uint(Ah[(m0 + g + 8) * LSTR + kb + tig + 4]);
                al[mt][0] = __float_as_uint(Al[(m0 + g    ) * LSTR + kb + tig    ]);
                al[mt][1] = __float_as_uint(Al[(m0 + g + 8) * LSTR + kb + tig    ]);
                al[mt][2] = __float_as_uint(Al[(m0 + g    ) * LSTR + kb + tig + 4]);
                al[mt][3] = __float_as_uint(Al[(m0 + g + 8) * LSTR + kb + tig + 4]);
            }
            uint32_t bh[8][2], bl[8][2];
#pragma unroll
            for (int nt = 0; nt < 8; nt++) {
                int n0 = wc * 64 + nt * 8;
                bh[nt][0] = __float_as_uint(Bh[(n0 + g) * LSTR + kb + tig    ]);
                bh[nt][1] = __float_as_uint(Bh[(n0 + g) * LSTR + kb + tig + 4]);
                bl[nt][0] = __float_as_uint(Bl[(n0 + g) * LSTR + kb + tig    ]);
                bl[nt][1] = __float_as_uint(Bl[(n0 + g) * LSTR + kb + tig + 4]);
            }
#pragma unroll
            for (int mt = 0; mt < 2; mt++)
#pragma unroll
                for (int nt = 0; nt < 8; nt++) {
                    mma_tf32_16x8x8(acc[mt][nt], ah[mt], bh[nt]);
                    mma_tf32_16x8x8(acc[mt][nt], ah[mt], bl[nt]);
                    mma_tf32_16x8x8(acc[mt][nt], al[mt], bh[nt]);
                }
        }
        __syncthreads();
    }

#pragma unroll
    for (int mt = 0; mt < 2; mt++) {
        int rb = rowBase + wr * 32 + mt * 16;
        int r0 = rb + g, r1 = rb + g + 8;
#pragma unroll
        for (int nt = 0; nt < 8; nt++) {
            int c = colBase + wc * 64 + nt * 8 + tig * 2;
            if (MODE == 2) {
                *(float2*)&O1[(size_t)r0 * N + c] =
                    make_float2(acc[mt][nt][0], acc[mt][nt][1]);
                *(float2*)&O1[(size_t)r1 * N + c] =
                    make_float2(acc[mt][nt][2], acc[mt][nt][3]);
            } else {
                float b0 = bias[c], b1v = bias[c + 1];
                float v00 = acc[mt][nt][0] + b0, v01 = acc[mt][nt][1] + b1v;
                float v10 = acc[mt][nt][2] + b0, v11 = acc[mt][nt][3] + b1v;
                v00 = 0.5f * v00 * (1.0f + erff(v00 * 0.70710678118654752f));
                v01 = 0.5f * v01 * (1.0f + erff(v01 * 0.70710678118654752f));
                v10 = 0.5f * v10 * (1.0f + erff(v10 * 0.70710678118654752f));
                v11 = 0.5f * v11 * (1.0f + erff(v11 * 0.70710678118654752f));
                float h00 = rna_tf32(v00), h01 = rna_tf32(v01);
                float h10 = rna_tf32(v10), h11 = rna_tf32(v11);
                *(float2*)&O1[(size_t)r0 * N + c] = make_float2(h00, h01);
                *(float2*)&O1[(size_t)r1 * N + c] = make_float2(h10, h11);
                *(float2*)&O2[(size_t)r0 * N + c] =
                    make_float2(rna_tf32(v00 - h00), rna_tf32(v01 - h01));
                *(float2*)&O2[(size_t)r1 * N + c] =
                    make_float2(rna_tf32(v10 - h10), rna_tf32(v11 - h11));
            }
        }
    }
}

// ---------------------------------------------------------------------------
// Reduce split-K partials: S2 = sum + bias; S2r = rna(S2)  (float4 vectorized)
__global__ void reduce_s2_kernel(const float* __restrict__ b2)
{
    int i4 = blockIdx.x * 256 + threadIdx.x;     // over ROWS*DM/4
    int row = i4 >> 8;                           // /(DM/4)
    if (row >= g_cnt[0]) return;
    size_t i = (size_t)i4 * 4;
    const float4 p0 = *(const float4*)&g_P[i];
    const float4 p1 = *(const float4*)&g_P[(size_t)ROWS * DM + i];
    const float4 p2 = *(const float4*)&g_P[2 * (size_t)ROWS * DM + i];
    const float4 p3 = *(const float4*)&g_P[3 * (size_t)ROWS * DM + i];
    int c = (i4 & 255) * 4;
    float4 bv = *(const float4*)&b2[c];
    float4 v;
    v.x = ((p0.x + p1.x) + (p2.x + p3.x)) + bv.x;
    v.y = ((p0.y + p1.y) + (p2.y + p3.y)) + bv.y;
    v.z = ((p0.z + p1.z) + (p2.z + p3.z)) + bv.z;
    v.w = ((p0.w + p1.w) + (p2.w + p3.w)) + bv.w;
    *(float4*)&g_S2[i] = v;
    float4 r;
    r.x = rna_tf32(v.x); r.y = rna_tf32(v.y);
    r.z = rna_tf32(v.z); r.w = rna_tf32(v.w);
    *(float4*)&g_S2r[i] = r;
}

// ---------------------------------------------------------------------------
#define NITERL (DM / KCH)
#define STG_F  (2 * TILE_F)

__global__ void __launch_bounds__(256, 1)
logits_kernel(const float* __restrict__ Ar, const float* __restrict__ Bt,
              const float* __restrict__ bq, float* __restrict__ q)
{
    const int nv4     = g_cnt[0];
    const int rowBase = blockIdx.x * 128;
    if (rowBase >= nv4) return;
    extern __shared__ float smem[];
    const uint32_t su = smem_u32(smem);
    const int tid     = threadIdx.x;
    const int colBase = blockIdx.y * 128;

    const int lane = tid & 31, wid = tid >> 5;
    const int wr = wid >> 1, wc = wid & 1;
    const int g  = lane >> 2, tig = lane & 3;

    float acc[2][8][4];
#pragma unroll
    for (int mt = 0; mt < 2; mt++)
#pragma unroll
        for (int nt = 0; nt < 8; nt++)
#pragma unroll
            for (int k = 0; k < 4; k++) acc[mt][nt][k] = 0.f;

    const float* agbase = Ar + (size_t)rowBase * DM;
    const float* bgbase = Bt + (size_t)colBase * DM;

    auto load_stage = [&](int s, int c) {
        uint32_t abase = su + (s * STG_F) * 4;
        uint32_t bbase = su + (s * STG_F + TILE_F) * 4;
        const float* ag = agbase + c * KCH;
        const float* bg = bgbase + c * KCH;
#pragma unroll
        for (int j = 0; j < 4; j++) {
            int idx = tid + 256 * j;
            int row = idx >> 3, seg = idx & 7;
            cp16(abase + (row * LSTR + seg * 4) * 4, ag + (size_t)row * DM + seg * 4);
        }
#pragma unroll
        for (int j = 0; j < 4; j++) {
            int idx = tid + 256 * j;
            int row = idx >> 3, seg = idx & 7;
            cp16(bbase + (row * LSTR + seg * 4) * 4, bg + (size_t)row * DM + seg * 4);
        }
    };

    load_stage(0, 0);
    CP_COMMIT();

    for (int it = 0; it < NITERL; it++) {
        int s = it & 1;
        CP_WAIT0();
        __syncthreads();
        if (it + 1 < NITERL) { load_stage(1 - s, it + 1); CP_COMMIT(); }

        const float* As = smem + s * STG_F;
        const float* Bs = smem + s * STG_F + TILE_F;

#pragma unroll
        for (int k8 = 0; k8 < 4; k8++) {
            int kb = k8 * 8;
            uint32_t a[2][4];
#pragma unroll
            for (int mt = 0; mt < 2; mt++) {
                int m0 = wr * 32 + mt * 16;
                a[mt][0] = __float_as_uint(As[(m0 + g    ) * LSTR + kb + tig    ]);
                a[mt][1] = __float_as_uint(As[(m0 + g + 8) * LSTR + kb + tig    ]);
                a[mt][2] = __float_as_uint(As[(m0 + g    ) * LSTR + kb + tig + 4]);
                a[mt][3] = __float_as_uint(As[(m0 + g + 8) * LSTR + kb + tig + 4]);
            }
            uint32_t b[8][2];
#pragma unroll
            for (int nt = 0; nt < 8; nt++) {
                int n0 = wc * 64 + nt * 8;
                b[nt][0] = __float_as_uint(Bs[(n0 + g) * LSTR + kb + tig    ]);
                b[nt][1] = __float_as_uint(Bs[(n0 + g) * LSTR + kb + tig + 4]);
            }
#pragma unroll
            for (int mt = 0; mt < 2; mt++)
#pragma unroll
                for (int nt = 0; nt < 8; nt++)
                    mma_tf32_16x8x8(acc[mt][nt], a[mt], b[nt]);
        }
        __syncthreads();
    }

#pragma unroll
    for (int mt = 0; mt < 2; mt++) {
        int rb  = rowBase + wr * 32 + mt * 16;
        int rc0 = rb + g, rc1 = rb + g + 8;
        int or0 = 0, or1 = 0;
        bool ok0 = rc0 < nv4, ok1 = rc1 < nv4;
        if (ok0) or0 = g_idx[rc0 >> 2] * 4 + (rc0 & 3);
        if (ok1) or1 = g_idx[rc1 >> 2] * 4 + (rc1 & 3);
#pragma unroll
        for (int nt = 0; nt < 8; nt++) {
            int c = colBase + wc * 64 + nt * 8 + tig * 2;
            float bq0 = bq[c], bq1 = bq[c + 1];
            if (ok0)
                *(float2*)&q[(size_t)or0 * VV + c] =
                    make_float2(acc[mt][nt][0] + bq0, acc[mt][nt][1] + bq1);
            if (ok1)
                *(float2*)&q[(size_t)or1 * VV + c] =
                    make_float2(acc[mt][nt][2] + bq0, acc[mt][nt][3] + bq1);
        }
    }
}

// ---------------------------------------------------------------------------
__global__ void beta_kernel(const float* __restrict__ Wb, const float* __restrict__ bbq,
                            float* __restrict__ obeta, float* __restrict__ ok)
{
    int rp = blockIdx.x;
    if (rp >= g_cnt[0]) return;
    int tid = threadIdx.x;
    const float* row = g_S2 + (size_t)rp * DM;
    float s = 0.f;
    for (int i = tid; i < DM; i += 256) s += row[i] * Wb[i];
    __shared__ float red[256];
    red[tid] = s; __syncthreads();
    for (int o = 128; o > 0; o >>= 1) { if (tid < o) red[tid] += red[tid + o]; __syncthreads(); }
    if (tid == 0) {
        float be = red[0] + bbq[0];
        int orow = g_idx[rp >> 2] * 4 + (rp & 3);
        obeta[orow]  = be;
        g_beta[orow] = be;
        float sig = 1.f / (1.f + expf(-be));
        int k = (int)ceilf(sig * 8.f);
        k = max(1, min(8, k));
        if (sig < 0.25f) k = 0;
        ok[orow] = (float)k;
    }
}

// ---------------------------------------------------------------------------
__global__ void nll_kernel(const float* __restrict__ q, const int* __restrict__ mask,
                           const int* __restrict__ labels)
{
    int r  = blockIdx.x;
    int d  = r & 3;
    int bt = r >> 2;
    int t  = bt % TT;
    int b  = bt / TT;
    int td = t + d + 1;
    bool valid = (td < TT) && (mask[bt] != 0) && (mask[b * TT + td] != 0);
    if (!valid) return;
    int tgt = labels[b * TT + td];

    const float* row = q + (size_t)r * VV;
    int tid = threadIdx.x;
    __shared__ float red[256];

    float mx = -INFINITY;
    for (int i = tid; i < VV; i += 256) mx = fmaxf(mx, row[i]);
    red[tid] = mx; __syncthreads();
    for (int o = 128; o > 0; o >>= 1) { if (tid < o) red[tid] = fmaxf(red[tid], red[tid + o]); __syncthreads(); }
    mx = red[0]; __syncthreads();

    float se = 0.f;
    for (int i = tid; i < VV; i += 256) se += expf(row[i] - mx);
    red[tid] = se; __syncthreads();
    for (int o = 128; o > 0; o >>= 1) { if (tid < o) red[tid] += red[tid + o]; __syncthreads(); }

    if (tid == 0) {
        float nll = logf(red[0]) + mx - row[tgt];
        atomicAdd(&g_acc[0], (double)nll);
        atomicAdd(&g_acc[1], 1.0);
    }
}

// ---------------------------------------------------------------------------
__global__ void bce_kernel(const int* __restrict__ mask)
{
    int idx = blockIdx.x * 256 + threadIdx.x;
    if (idx >= BTN) return;
    int t = idx % TT;
    int b = idx / TT;
    if (mask[idx] == 0) return;
    float bsum = 0.f;
    bool anyv = false;
#pragma unroll
    for (int d = 0; d < 4; d++) {
        int td = t + d + 1;
        bool valid = (td < TT) && (mask[b * TT + td] != 0);
        float be  = g_beta[idx * 4 + d];
        float bce = fmaxf(be, 0.f) + log1pf(expf(-fabsf(be))) - (valid ? be : 0.f);
        bsum += bce;
        anyv |= valid;
    }
    if (anyv) {
        atomicAdd(&g_acc[2], (double)bsum);
        atomicAdd(&g_acc[3], 1.0);
    }
}

// ---------------------------------------------------------------------------
__global__ void fin_kernel(float* __restrict__ oloss)
{
    double cnt = g_acc[1];
    double Lq  = (cnt > 0.0) ? g_acc[0] / cnt : 0.0;
    double den = g_acc[3]; if (den < 1.0) den = 1.0;
    double Lb  = g_acc[2] / den;
    oloss[0] = (float)(Lq + Lb);
}

// ---------------------------------------------------------------------------
extern "C" void kernel_launch(void* const* d_in, const int* in_sizes, int n_in,
                              void* d_out, int out_size)
{
    const float* H      = (const float*)d_in[0];
    const int*   ids    = (const int*)  d_in[1];
    const int*   mask   = (const int*)  d_in[2];
    const int*   labels = (const int*)  d_in[3];
    const float* emb    = (const float*)d_in[4];
    const float* demb   = (const float*)d_in[5];
    const float* ln_g   = (const float*)d_in[6];
    const float* ln_b   = (const float*)d_in[7];
    const float* W1     = (const float*)d_in[8];
    const float* b1     = (const float*)d_in[9];
    const float* W2     = (const float*)d_in[10];
    const float* b2     = (const float*)d_in[11];
    const float* Wq     = (const float*)d_in[12];
    const float* bq     = (const float*)d_in[13];
    const float* Wb     = (const float*)d_in[14];
    const float* bb     = (const float*)d_in[15];

    float* out   = (float*)d_out;
    float* q     = out;
    float* obeta = out + (size_t)ROWS * VV;
    float* ok    = obeta + ROWS;
    float* oloss = ok + ROWS;

    void *pShi, *pSlo, *pGhi, *pGlo, *pW1h, *pW1l, *pW2h, *pW2l, *pP, *pS2r, *pWt;
    cudaGetSymbolAddress(&pShi, g_Shi);
    cudaGetSymbolAddress(&pSlo, g_Slo);
    cudaGetSymbolAddress(&pGhi, g_Ghi);
    cudaGetSymbolAddress(&pGlo, g_Glo);
    cudaGetSymbolAddress(&pW1h, g_W1thi);
    cudaGetSymbolAddress(&pW1l, g_W1tlo);
    cudaGetSymbolAddress(&pW2h, g_W2thi);
    cudaGetSymbolAddress(&pW2l, g_W2tlo);
    cudaGetSymbolAddress(&pP,   g_P);
    cudaGetSymbolAddress(&pS2r, g_S2r);
    cudaGetSymbolAddress(&pWt,  g_Wt);

    const int smemL = 2 * STG_F * 4;
    cudaFuncSetAttribute(logits_kernel,
                         cudaFuncAttributeMaxDynamicSharedMemorySize, smemL);
    cudaFuncSetAttribute(mlp3_kernel<0>,
                         cudaFuncAttributeMaxDynamicSharedMemorySize, SM3_BYTES);
    cudaFuncSetAttribute(mlp3_kernel<2>,
                         cudaFuncAttributeMaxDynamicSharedMemorySize, SM3_BYTES);

    zero_acc_kernel<<<1, 32>>>();
    compact_kernel<<<1, BTN>>>(mask);
    zero_fill_kernel<<<BTN, 256>>>(mask, q, obeta, ok);

    transpose_round_kernel<<<dim3(VV / 32, DM / 32), dim3(32, 8)>>>(Wq);
    transpose_split_kernel<<<dim3(DH / 32, DM / 32), dim3(32, 8)>>>(
        W1, (float*)pW1h, (float*)pW1l, DM, DH);
    transpose_split_kernel<<<dim3(DM / 32, DH / 32), dim3(32, 8)>>>(
        W2, (float*)pW2h, (float*)pW2l, DH, DM);

    s_kernel<<<ROWS, 256>>>(H, ids, emb, demb, ln_g, ln_b);

    // G(hi/lo) = gelu(S @ W1 + b1)
    mlp3_kernel<0><<<dim3(ROWS / 128, DH / 128), 256, SM3_BYTES>>>(
        (const float*)pShi, (const float*)pSlo,
        (const float*)pW1h, (const float*)pW1l,
        b1, (float*)pGhi, (float*)pGlo, DH, DM);

    // Split-K partials for S2 = G @ W2
    mlp3_kernel<2><<<dim3(ROWS / 128, DM / 128, SPLITK), 256, SM3_BYTES>>>(
        (const float*)pGhi, (const float*)pGlo,
        (const float*)pW2h, (const float*)pW2l,
        nullptr, (float*)pP, nullptr, DM, DH);

    reduce_s2_kernel<<<ROWS * DM / 1024, 256>>>(b2);

    logits_kernel<<<dim3(ROWS / 128, VV / 128), 256, smemL>>>(
        (const float*)pS2r, (const float*)pWt, bq, q);

    beta_kernel<<<ROWS, 256>>>(Wb, bb, obeta, ok);

    nll_kernel<<<ROWS, 256>>>(q, mask, labels);
    bce_kernel<<<(BTN + 255) / 256, 256>>>(mask);
    fin_kernel<<<1, 1>>>(oloss);

    (void)in_sizes; (void)n_in; (void)out_size;
}

// round 7
// speedup vs baseline: 1.1233x; 1.1233x over previous
#include <cuda_runtime.h>
#include <math.h>
#include <stdint.h>

// Problem constants
#define BB   2
#define TT   512
#define DM   1024
#define DH   4096
#define DD   4
#define VV   32000
#define ROWS (BB*TT*DD)   // 4096
#define BTN  (BB*TT)      // 1024
#define SPLITK 4

// Scratch (static device globals — no allocation allowed)
__device__ float  g_S  [ROWS*DM];         // raw LN output
__device__ float  g_G  [ROWS*DH];         // raw gelu(MLP hidden)
__device__ float  g_P  [SPLITK*ROWS*DM];  // split-K partials for S2
__device__ float  g_S2 [ROWS*DM];         // exact fp32 S2 (compacted rows)
__device__ float  g_S2r[ROWS*DM];         // tf32-rounded S2 (compacted rows)
__device__ float  g_beta[ROWS];           // orig indexing
__device__ int    g_idx [BTN];
__device__ int    g_cnt [1];
__device__ double g_acc[4];

// ============================================================================
__device__ __forceinline__ uint32_t smem_u32(const void* p) {
    uint32_t a;
    asm("{ .reg .u64 t; cvta.to.shared.u64 t, %1; cvt.u32.u64 %0, t; }"
        : "=r"(a) : "l"(p));
    return a;
}
__device__ __forceinline__ float rna_tf32(float v) {
    uint32_t r;
    asm("cvt.rna.tf32.f32 %0, %1;" : "=r"(r) : "f"(v));
    return __uint_as_float(r);
}
__device__ __forceinline__ void split2(float v, uint32_t& hi, uint32_t& lo) {
    float h = rna_tf32(v);
    hi = __float_as_uint(h);
    lo = __float_as_uint(rna_tf32(v - h));
}
__device__ __forceinline__ void cp16(uint32_t s, const void* g) {
    asm volatile("cp.async.cg.shared.global [%0], [%1], 16;" :: "r"(s), "l"(g));
}
#define CP_COMMIT() asm volatile("cp.async.commit_group;" ::: "memory")
#define CP_WAIT0()  asm volatile("cp.async.wait_group 0;" ::: "memory")

__device__ __forceinline__ void mma_tf32_16x8x8(float* d, const uint32_t* a,
                                                const uint32_t* b) {
    asm volatile(
        "mma.sync.aligned.m16n8k8.row.col.f32.tf32.tf32.f32 "
        "{%0,%1,%2,%3}, {%4,%5,%6,%7}, {%8,%9}, {%0,%1,%2,%3};"
        : "+f"(d[0]), "+f"(d[1]), "+f"(d[2]), "+f"(d[3])
        : "r"(a[0]), "r"(a[1]), "r"(a[2]), "r"(a[3]), "r"(b[0]), "r"(b[1]));
}

// ============================================================================
__global__ void zero_acc_kernel() {
    if (threadIdx.x < 4) g_acc[threadIdx.x] = 0.0;
}

// ---------------------------------------------------------------------------
__global__ void compact_kernel(const int* __restrict__ mask) {
    __shared__ int pre[BTN];
    int tid = threadIdx.x;
    int m = (mask[tid] != 0) ? 1 : 0;
    pre[tid] = m;
    __syncthreads();
    for (int o = 1; o < BTN; o <<= 1) {
        int v = (tid >= o) ? pre[tid - o] : 0;
        __syncthreads();
        pre[tid] += v;
        __syncthreads();
    }
    int mv = pre[BTN - 1];
    if (m) g_idx[pre[tid] - 1] = tid;
    if (tid >= mv) g_idx[tid] = 0;
    if (tid == 0) g_cnt[0] = mv * 4;
}

// ---------------------------------------------------------------------------
__global__ void zero_fill_kernel(const int* __restrict__ mask,
                                 float* __restrict__ q,
                                 float* __restrict__ obeta,
                                 float* __restrict__ ok)
{
    int bt = blockIdx.x;
    if (mask[bt] != 0) return;
    int tid = threadIdx.x;
    float4* dst = (float4*)(q + (size_t)bt * 4 * VV);
#pragma unroll 4
    for (int i = tid; i < 32000; i += 256) dst[i] = make_float4(0.f, 0.f, 0.f, 0.f);
    if (tid < 4) {
        obeta[bt * 4 + tid] = 0.f;
        ok[bt * 4 + tid]    = 0.f;
    }
}

// ---------------------------------------------------------------------------
// S = LayerNorm(H + emb[ids] + depth_emb[d]) * g + b  (raw fp32, compacted)
__global__ void s_kernel(const float* __restrict__ H, const int* __restrict__ ids,
                         const float* __restrict__ emb, const float* __restrict__ demb,
                         const float* __restrict__ lng, const float* __restrict__ lnb)
{
    int rp = blockIdx.x;
    if (rp >= g_cnt[0]) return;
    int bt  = g_idx[rp >> 2];
    int d   = rp & 3;
    int tid = threadIdx.x;

    const float* hrow = H    + (size_t)bt * DM;
    const float* erow = emb  + (size_t)ids[bt] * DM;
    const float* drow = demb + (size_t)d * DM;

    float x[4];
    float s = 0.f;
#pragma unroll
    for (int j = 0; j < 4; j++) {
        int i = j * 256 + tid;
        x[j] = hrow[i] + erow[i] + drow[i];
        s += x[j];
    }
    __shared__ float red[256];
    red[tid] = s; __syncthreads();
    for (int o = 128; o > 0; o >>= 1) { if (tid < o) red[tid] += red[tid + o]; __syncthreads(); }
    float mu = red[0] * (1.0f / DM);
    __syncthreads();

    float v = 0.f;
#pragma unroll
    for (int j = 0; j < 4; j++) { float dx = x[j] - mu; v += dx * dx; }
    red[tid] = v; __syncthreads();
    for (int o = 128; o > 0; o >>= 1) { if (tid < o) red[tid] += red[tid + o]; __syncthreads(); }
    float inv = rsqrtf(red[0] * (1.0f / DM) + 1e-5f);

#pragma unroll
    for (int j = 0; j < 4; j++) {
        int i = j * 256 + tid;
        g_S[(size_t)rp * DM + i] = (x[j] - mu) * inv * lng[i] + lnb[i];
    }
}

// ---------------------------------------------------------------------------
// GEMM geometry: A tile 128(m)x32(k) stride 36; B tile 32(k)x128(n) stride 136
#define KCH     32
#define ASTR    36
#define BSTR    136
#define A_TILE_F (128 * ASTR)          // 4608
#define B_TILE_F (KCH * BSTR)          // 4352
#define STAGE_F  (A_TILE_F + B_TILE_F) // 8960
#define SM_BYTES (2 * STAGE_F * 4)     // 71680

// ---------------------------------------------------------------------------
// 3xTF32 GEMM, raw operands, in-register hi/lo split.
// A: raw [M,K] row-major (compacted rows). B: raw W [K,N] row-major (no transpose).
// MODE 0: O1 = gelu(acc + bias), full K           (G = gelu(S@W1+b1))
// MODE 2: split-K partial, raw acc -> O1 partials (P_z = G@W2 chunk)
template<int MODE>
__global__ void __launch_bounds__(256, 2)
mlp3_kernel(const float* __restrict__ A, const float* __restrict__ W,
            const float* __restrict__ bias,
            float* __restrict__ O1, int N, int K)
{
    const int rowBase = blockIdx.x * 128;
    if (rowBase >= g_cnt[0]) return;
    extern __shared__ float smem[];
    const uint32_t su = smem_u32(smem);
    const int tid     = threadIdx.x;
    const int colBase = blockIdx.y * 128;

    int koff  = 0;
    int niter = K / KCH;
    if (MODE == 2) {
        koff  = blockIdx.z * (K / SPLITK);
        niter = K / SPLITK / KCH;
        O1   += (size_t)blockIdx.z * ROWS * DM;
    }

    const int lane = tid & 31, wid = tid >> 5;
    const int wr = wid >> 1, wc = wid & 1;
    const int g  = lane >> 2, tig = lane & 3;

    float acc[2][8][4];
#pragma unroll
    for (int mt = 0; mt < 2; mt++)
#pragma unroll
        for (int nt = 0; nt < 8; nt++)
#pragma unroll
            for (int k = 0; k < 4; k++) acc[mt][nt][k] = 0.f;

    const float* abase = A + (size_t)rowBase * K + koff;
    const float* bbase = W + (size_t)koff * N + colBase;

    auto load_stage = [&](int s, int c) {
        uint32_t sa = su + (s * STAGE_F) * 4;
        uint32_t sb = su + (s * STAGE_F + A_TILE_F) * 4;
        const float* ag = abase + c * KCH;
        const float* bg = bbase + (size_t)c * KCH * N;
#pragma unroll
        for (int j = 0; j < 4; j++) {             // A: 1024 segs
            int idx = tid + 256 * j;
            int row = idx >> 3, seg = idx & 7;
            cp16(sa + (row * ASTR + seg * 4) * 4, ag + (size_t)row * K + seg * 4);
        }
#pragma unroll
        for (int j = 0; j < 4; j++) {             // B: 1024 segs
            int idx = tid + 256 * j;
            int row = idx >> 5, seg = idx & 31;
            cp16(sb + (row * BSTR + seg * 4) * 4, bg + (size_t)row * N + seg * 4);
        }
    };

    load_stage(0, 0);
    CP_COMMIT();

    for (int it = 0; it < niter; it++) {
        int s = it & 1;
        CP_WAIT0();
        __syncthreads();
        if (it + 1 < niter) { load_stage(1 - s, it + 1); CP_COMMIT(); }

        const float* As = smem + s * STAGE_F;
        const float* Bs = smem + s * STAGE_F + A_TILE_F;

#pragma unroll
        for (int k8 = 0; k8 < 4; k8++) {
            int kb = k8 * 8;
            uint32_t ah[2][4], al[2][4];
#pragma unroll
            for (int mt = 0; mt < 2; mt++) {
                int m0 = wr * 32 + mt * 16;
                split2(As[(m0 + g    ) * ASTR + kb + tig    ], ah[mt][0], al[mt][0]);
                split2(As[(m0 + g + 8) * ASTR + kb + tig    ], ah[mt][1], al[mt][1]);
                split2(As[(m0 + g    ) * ASTR + kb + tig + 4], ah[mt][2], al[mt][2]);
                split2(As[(m0 + g + 8) * ASTR + kb + tig + 4], ah[mt][3], al[mt][3]);
            }
            uint32_t bh[8][2], bl[8][2];
#pragma unroll
            for (int nt = 0; nt < 8; nt++) {
                int n0 = wc * 64 + nt * 8;
                split2(Bs[(kb + tig    ) * BSTR + n0 + g], bh[nt][0], bl[nt][0]);
                split2(Bs[(kb + tig + 4) * BSTR + n0 + g], bh[nt][1], bl[nt][1]);
            }
#pragma unroll
            for (int mt = 0; mt < 2; mt++)
#pragma unroll
                for (int nt = 0; nt < 8; nt++) {
                    mma_tf32_16x8x8(acc[mt][nt], ah[mt], bh[nt]);
                    mma_tf32_16x8x8(acc[mt][nt], ah[mt], bl[nt]);
                    mma_tf32_16x8x8(acc[mt][nt], al[mt], bh[nt]);
                }
        }
        __syncthreads();
    }

#pragma unroll
    for (int mt = 0; mt < 2; mt++) {
        int rb = rowBase + wr * 32 + mt * 16;
        int r0 = rb + g, r1 = rb + g + 8;
#pragma unroll
        for (int nt = 0; nt < 8; nt++) {
            int c = colBase + wc * 64 + nt * 8 + tig * 2;
            if (MODE == 2) {
                *(float2*)&O1[(size_t)r0 * N + c] =
                    make_float2(acc[mt][nt][0], acc[mt][nt][1]);
                *(float2*)&O1[(size_t)r1 * N + c] =
                    make_float2(acc[mt][nt][2], acc[mt][nt][3]);
            } else {
                float b0 = bias[c], b1v = bias[c + 1];
                float v00 = acc[mt][nt][0] + b0, v01 = acc[mt][nt][1] + b1v;
                float v10 = acc[mt][nt][2] + b0, v11 = acc[mt][nt][3] + b1v;
                v00 = 0.5f * v00 * (1.0f + erff(v00 * 0.70710678118654752f));
                v01 = 0.5f * v01 * (1.0f + erff(v01 * 0.70710678118654752f));
                v10 = 0.5f * v10 * (1.0f + erff(v10 * 0.70710678118654752f));
                v11 = 0.5f * v11 * (1.0f + erff(v11 * 0.70710678118654752f));
                *(float2*)&O1[(size_t)r0 * N + c] = make_float2(v00, v01);
                *(float2*)&O1[(size_t)r1 * N + c] = make_float2(v10, v11);
            }
        }
    }
}

// ---------------------------------------------------------------------------
// Reduce split-K partials: S2 = sum + bias; S2r = rna(S2)
__global__ void reduce_s2_kernel(const float* __restrict__ b2)
{
    int i4 = blockIdx.x * 256 + threadIdx.x;
    int row = i4 >> 8;
    if (row >= g_cnt[0]) return;
    size_t i = (size_t)i4 * 4;
    const float4 p0 = *(const float4*)&g_P[i];
    const float4 p1 = *(const float4*)&g_P[(size_t)ROWS * DM + i];
    const float4 p2 = *(const float4*)&g_P[2 * (size_t)ROWS * DM + i];
    const float4 p3 = *(const float4*)&g_P[3 * (size_t)ROWS * DM + i];
    int c = (i4 & 255) * 4;
    float4 bv = *(const float4*)&b2[c];
    float4 v;
    v.x = ((p0.x + p1.x) + (p2.x + p3.x)) + bv.x;
    v.y = ((p0.y + p1.y) + (p2.y + p3.y)) + bv.y;
    v.z = ((p0.z + p1.z) + (p2.z + p3.z)) + bv.z;
    v.w = ((p0.w + p1.w) + (p2.w + p3.w)) + bv.w;
    *(float4*)&g_S2[i] = v;
    float4 r;
    r.x = rna_tf32(v.x); r.y = rna_tf32(v.y);
    r.z = rna_tf32(v.z); r.w = rna_tf32(v.w);
    *(float4*)&g_S2r[i] = r;
}

// ---------------------------------------------------------------------------
// tf32 logits GEMM: A = S2r (pre-rounded), B = Wq[K][N] read directly
// (in-register rna cvt); scatter epilogue to original q rows.
__global__ void __launch_bounds__(256, 2)
logits_kernel(const float* __restrict__ Ar, const float* __restrict__ Wq,
              const float* __restrict__ bq, float* __restrict__ q)
{
    const int nv4     = g_cnt[0];
    const int rowBase = blockIdx.x * 128;
    if (rowBase >= nv4) return;
    extern __shared__ float smem[];
    const uint32_t su = smem_u32(smem);
    const int tid     = threadIdx.x;
    const int colBase = blockIdx.y * 128;

    const int lane = tid & 31, wid = tid >> 5;
    const int wr = wid >> 1, wc = wid & 1;
    const int g  = lane >> 2, tig = lane & 3;

    float acc[2][8][4];
#pragma unroll
    for (int mt = 0; mt < 2; mt++)
#pragma unroll
        for (int nt = 0; nt < 8; nt++)
#pragma unroll
            for (int k = 0; k < 4; k++) acc[mt][nt][k] = 0.f;

    const float* abase = Ar + (size_t)rowBase * DM;
    const float* bbase = Wq + colBase;

    auto load_stage = [&](int s, int c) {
        uint32_t sa = su + (s * STAGE_F) * 4;
        uint32_t sb = su + (s * STAGE_F + A_TILE_F) * 4;
        const float* ag = abase + c * KCH;
        const float* bg = bbase + (size_t)c * KCH * VV;
#pragma unroll
        for (int j = 0; j < 4; j++) {
            int idx = tid + 256 * j;
            int row = idx >> 3, seg = idx & 7;
            cp16(sa + (row * ASTR + seg * 4) * 4, ag + (size_t)row * DM + seg * 4);
        }
#pragma unroll
        for (int j = 0; j < 4; j++) {
            int idx = tid + 256 * j;
            int row = idx >> 5, seg = idx & 31;
            cp16(sb + (row * BSTR + seg * 4) * 4, bg + (size_t)row * VV + seg * 4);
        }
    };

    load_stage(0, 0);
    CP_COMMIT();

    const int NITERL = DM / KCH;
    for (int it = 0; it < NITERL; it++) {
        int s = it & 1;
        CP_WAIT0();
        __syncthreads();
        if (it + 1 < NITERL) { load_stage(1 - s, it + 1); CP_COMMIT(); }

        const float* As = smem + s * STAGE_F;
        const float* Bs = smem + s * STAGE_F + A_TILE_F;

#pragma unroll
        for (int k8 = 0; k8 < 4; k8++) {
            int kb = k8 * 8;
            uint32_t a[2][4];
#pragma unroll
            for (int mt = 0; mt < 2; mt++) {
                int m0 = wr * 32 + mt * 16;
                a[mt][0] = __float_as_uint(As[(m0 + g    ) * ASTR + kb + tig    ]);
                a[mt][1] = __float_as_uint(As[(m0 + g + 8) * ASTR + kb + tig    ]);
                a[mt][2] = __float_as_uint(As[(m0 + g    ) * ASTR + kb + tig + 4]);
                a[mt][3] = __float_as_uint(As[(m0 + g + 8) * ASTR + kb + tig + 4]);
            }
            uint32_t b[8][2];
#pragma unroll
            for (int nt = 0; nt < 8; nt++) {
                int n0 = wc * 64 + nt * 8;
                b[nt][0] = __float_as_uint(rna_tf32(Bs[(kb + tig    ) * BSTR + n0 + g]));
                b[nt][1] = __float_as_uint(rna_tf32(Bs[(kb + tig + 4) * BSTR + n0 + g]));
            }
#pragma unroll
            for (int mt = 0; mt < 2; mt++)
#pragma unroll
                for (int nt = 0; nt < 8; nt++)
                    mma_tf32_16x8x8(acc[mt][nt], a[mt], b[nt]);
        }
        __syncthreads();
    }

#pragma unroll
    for (int mt = 0; mt < 2; mt++) {
        int rb  = rowBase + wr * 32 + mt * 16;
        int rc0 = rb + g, rc1 = rb + g + 8;
        int or0 = 0, or1 = 0;
        bool ok0 = rc0 < nv4, ok1 = rc1 < nv4;
        if (ok0) or0 = g_idx[rc0 >> 2] * 4 + (rc0 & 3);
        if (ok1) or1 = g_idx[rc1 >> 2] * 4 + (rc1 & 3);
#pragma unroll
        for (int nt = 0; nt < 8; nt++) {
            int c = colBase + wc * 64 + nt * 8 + tig * 2;
            float bq0 = bq[c], bq1 = bq[c + 1];
            if (ok0)
                *(float2*)&q[(size_t)or0 * VV + c] =
                    make_float2(acc[mt][nt][0] + bq0, acc[mt][nt][1] + bq1);
            if (ok1)
                *(float2*)&q[(size_t)or1 * VV + c] =
                    make_float2(acc[mt][nt][2] + bq0, acc[mt][nt][3] + bq1);
        }
    }
}

// ---------------------------------------------------------------------------
__global__ void beta_kernel(const float* __restrict__ Wb, const float* __restrict__ bbq,
                            float* __restrict__ obeta, float* __restrict__ ok)
{
    int rp = blockIdx.x;
    if (rp >= g_cnt[0]) return;
    int tid = threadIdx.x;
    const float* row = g_S2 + (size_t)rp * DM;
    float s = 0.f;
    for (int i = tid; i < DM; i += 256) s += row[i] * Wb[i];
    __shared__ float red[256];
    red[tid] = s; __syncthreads();
    for (int o = 128; o > 0; o >>= 1) { if (tid < o) red[tid] += red[tid + o]; __syncthreads(); }
    if (tid == 0) {
        float be = red[0] + bbq[0];
        int orow = g_idx[rp >> 2] * 4 + (rp & 3);
        obeta[orow]  = be;
        g_beta[orow] = be;
        float sig = 1.f / (1.f + expf(-be));
        int k = (int)ceilf(sig * 8.f);
        k = max(1, min(8, k));
        if (sig < 0.25f) k = 0;
        ok[orow] = (float)k;
    }
}

// ---------------------------------------------------------------------------
__global__ void nll_kernel(const float* __restrict__ q, const int* __restrict__ mask,
                           const int* __restrict__ labels)
{
    int r  = blockIdx.x;
    int d  = r & 3;
    int bt = r >> 2;
    int t  = bt % TT;
    int b  = bt / TT;
    int td = t + d + 1;
    bool valid = (td < TT) && (mask[bt] != 0) && (mask[b * TT + td] != 0);
    if (!valid) return;
    int tgt = labels[b * TT + td];

    const float* row = q + (size_t)r * VV;
    int tid = threadIdx.x;
    __shared__ float red[256];

    float mx = -INFINITY;
    for (int i = tid; i < VV; i += 256) mx = fmaxf(mx, row[i]);
    red[tid] = mx; __syncthreads();
    for (int o = 128; o > 0; o >>= 1) { if (tid < o) red[tid] = fmaxf(red[tid], red[tid + o]); __syncthreads(); }
    mx = red[0]; __syncthreads();

    float se = 0.f;
    for (int i = tid; i < VV; i += 256) se += expf(row[i] - mx);
    red[tid] = se; __syncthreads();
    for (int o = 128; o > 0; o >>= 1) { if (tid < o) red[tid] += red[tid + o]; __syncthreads(); }

    if (tid == 0) {
        float nll = logf(red[0]) + mx - row[tgt];
        atomicAdd(&g_acc[0], (double)nll);
        atomicAdd(&g_acc[1], 1.0);
    }
}

// ---------------------------------------------------------------------------
__global__ void bce_kernel(const int* __restrict__ mask)
{
    int idx = blockIdx.x * 256 + threadIdx.x;
    if (idx >= BTN) return;
    int t = idx % TT;
    int b = idx / TT;
    if (mask[idx] == 0) return;
    float bsum = 0.f;
    bool anyv = false;
#pragma unroll
    for (int d = 0; d < 4; d++) {
        int td = t + d + 1;
        bool valid = (td < TT) && (mask[b * TT + td] != 0);
        float be  = g_beta[idx * 4 + d];
        float bce = fmaxf(be, 0.f) + log1pf(expf(-fabsf(be))) - (valid ? be : 0.f);
        bsum += bce;
        anyv |= valid;
    }
    if (anyv) {
        atomicAdd(&g_acc[2], (double)bsum);
        atomicAdd(&g_acc[3], 1.0);
    }
}

// ---------------------------------------------------------------------------
__global__ void fin_kernel(float* __restrict__ oloss)
{
    double cnt = g_acc[1];
    double Lq  = (cnt > 0.0) ? g_acc[0] / cnt : 0.0;
    double den = g_acc[3]; if (den < 1.0) den = 1.0;
    double Lb  = g_acc[2] / den;
    oloss[0] = (float)(Lq + Lb);
}

// ---------------------------------------------------------------------------
extern "C" void kernel_launch(void* const* d_in, const int* in_sizes, int n_in,
                              void* d_out, int out_size)
{
    const float* H      = (const float*)d_in[0];
    const int*   ids    = (const int*)  d_in[1];
    const int*   mask   = (const int*)  d_in[2];
    const int*   labels = (const int*)  d_in[3];
    const float* emb    = (const float*)d_in[4];
    const float* demb   = (const float*)d_in[5];
    const float* ln_g   = (const float*)d_in[6];
    const float* ln_b   = (const float*)d_in[7];
    const float* W1     = (const float*)d_in[8];
    const float* b1     = (const float*)d_in[9];
    const float* W2     = (const float*)d_in[10];
    const float* b2     = (const float*)d_in[11];
    const float* Wq     = (const float*)d_in[12];
    const float* bq     = (const float*)d_in[13];
    const float* Wb     = (const float*)d_in[14];
    const float* bb     = (const float*)d_in[15];

    float* out   = (float*)d_out;
    float* q     = out;
    float* obeta = out + (size_t)ROWS * VV;
    float* ok    = obeta + ROWS;
    float* oloss = ok + ROWS;

    void *pS, *pG, *pP, *pS2r;
    cudaGetSymbolAddress(&pS,   g_S);
    cudaGetSymbolAddress(&pG,   g_G);
    cudaGetSymbolAddress(&pP,   g_P);
    cudaGetSymbolAddress(&pS2r, g_S2r);

    cudaFuncSetAttribute(logits_kernel,
                         cudaFuncAttributeMaxDynamicSharedMemorySize, SM_BYTES);
    cudaFuncSetAttribute(mlp3_kernel<0>,
                         cudaFuncAttributeMaxDynamicSharedMemorySize, SM_BYTES);
    cudaFuncSetAttribute(mlp3_kernel<2>,
                         cudaFuncAttributeMaxDynamicSharedMemorySize, SM_BYTES);

    zero_acc_kernel<<<1, 32>>>();
    compact_kernel<<<1, BTN>>>(mask);
    zero_fill_kernel<<<BTN, 256>>>(mask, q, obeta, ok);

    s_kernel<<<ROWS, 256>>>(H, ids, emb, demb, ln_g, ln_b);

    // G = gelu(S @ W1 + b1) — W1 read untransposed, split in-register
    mlp3_kernel<0><<<dim3(ROWS / 128, DH / 128), 256, SM_BYTES>>>(
        (const float*)pS, W1, b1, (float*)pG, DH, DM);

    // Split-K partials for S2 = G @ W2
    mlp3_kernel<2><<<dim3(ROWS / 128, DM / 128, SPLITK), 256, SM_BYTES>>>(
        (const float*)pG, W2, nullptr, (float*)pP, DM, DH);

    reduce_s2_kernel<<<ROWS * DM / 1024, 256>>>(b2);

    // q = scatter(S2r @ Wq + bq) — Wq read untransposed, cvt in-register
    logits_kernel<<<dim3(ROWS / 128, VV / 128), 256, SM_BYTES>>>(
        (const float*)pS2r, Wq, bq, q);

    beta_kernel<<<ROWS, 256>>>(Wb, bb, obeta, ok);

    nll_kernel<<<ROWS, 256>>>(q, mask, labels);
    bce_kernel<<<(BTN + 255) / 256, 256>>>(mask);
    fin_kernel<<<1, 1>>>(oloss);

    (void)in_sizes; (void)n_in; (void)out_size;
}

// round 8
// speedup vs baseline: 1.6345x; 1.4551x over previous
#include <cuda_runtime.h>
#include <cuda_fp16.h>
#include <math.h>
#include <stdint.h>

// Problem constants
#define BB   2
#define TT   512
#define DM   1024
#define DH   4096
#define DD   4
#define VV   32000
#define ROWS (BB*TT*DD)   // 4096
#define BTN  (BB*TT)      // 1024
#define SPLITK 4

// Scratch (static device globals — no allocation allowed)
__device__ float   g_S  [ROWS*DM];         // raw LN output
__device__ float   g_G  [ROWS*DH];         // raw gelu(MLP hidden), fp32-exact
__device__ float   g_P  [SPLITK*ROWS*DM];  // split-K partials for S2
__device__ __half  g_S2h[ROWS*DM];         // fp16 S2 (compacted rows)
__device__ __half2 g_Wqh[(DM/2)*VV];       // Wq packed [k/2][n] as half2
__device__ float   g_w2b[DH+1];            // W2@Wb (+ cb in last slot)
__device__ float   g_beta[ROWS];           // orig indexing
__device__ int     g_idx [BTN];
__device__ int     g_cnt [1];
__device__ double  g_acc[4];

// ============================================================================
__device__ __forceinline__ uint32_t smem_u32(const void* p) {
    uint32_t a;
    asm("{ .reg .u64 t; cvta.to.shared.u64 t, %1; cvt.u32.u64 %0, t; }"
        : "=r"(a) : "l"(p));
    return a;
}
__device__ __forceinline__ float rna_tf32(float v) {
    uint32_t r;
    asm("cvt.rna.tf32.f32 %0, %1;" : "=r"(r) : "f"(v));
    return __uint_as_float(r);
}
__device__ __forceinline__ void split2(float v, uint32_t& hi, uint32_t& lo) {
    float h = rna_tf32(v);
    hi = __float_as_uint(h);
    lo = __float_as_uint(rna_tf32(v - h));
}
__device__ __forceinline__ void cp16(uint32_t s, const void* g) {
    asm volatile("cp.async.cg.shared.global [%0], [%1], 16;" :: "r"(s), "l"(g));
}
#define CP_COMMIT() asm volatile("cp.async.commit_group;" ::: "memory")
#define CP_WAIT0()  asm volatile("cp.async.wait_group 0;" ::: "memory")

__device__ __forceinline__ void mma_tf32_16x8x8(float* d, const uint32_t* a,
                                                const uint32_t* b) {
    asm volatile(
        "mma.sync.aligned.m16n8k8.row.col.f32.tf32.tf32.f32 "
        "{%0,%1,%2,%3}, {%4,%5,%6,%7}, {%8,%9}, {%0,%1,%2,%3};"
        : "+f"(d[0]), "+f"(d[1]), "+f"(d[2]), "+f"(d[3])
        : "r"(a[0]), "r"(a[1]), "r"(a[2]), "r"(a[3]), "r"(b[0]), "r"(b[1]));
}
__device__ __forceinline__ void mma_f16_16x8x16(float* d, const uint32_t* a,
                                                const uint32_t* b) {
    asm volatile(
        "mma.sync.aligned.m16n8k16.row.col.f32.f16.f16.f32 "
        "{%0,%1,%2,%3}, {%4,%5,%6,%7}, {%8,%9}, {%0,%1,%2,%3};"
        : "+f"(d[0]), "+f"(d[1]), "+f"(d[2]), "+f"(d[3])
        : "r"(a[0]), "r"(a[1]), "r"(a[2]), "r"(a[3]), "r"(b[0]), "r"(b[1]));
}

// ============================================================================
__global__ void zero_acc_kernel() {
    if (threadIdx.x < 4) g_acc[threadIdx.x] = 0.0;
}

// ---------------------------------------------------------------------------
__global__ void compact_kernel(const int* __restrict__ mask) {
    __shared__ int pre[BTN];
    int tid = threadIdx.x;
    int m = (mask[tid] != 0) ? 1 : 0;
    pre[tid] = m;
    __syncthreads();
    for (int o = 1; o < BTN; o <<= 1) {
        int v = (tid >= o) ? pre[tid - o] : 0;
        __syncthreads();
        pre[tid] += v;
        __syncthreads();
    }
    int mv = pre[BTN - 1];
    if (m) g_idx[pre[tid] - 1] = tid;
    if (tid >= mv) g_idx[tid] = 0;
    if (tid == 0) g_cnt[0] = mv * 4;
}

// ---------------------------------------------------------------------------
__global__ void zero_fill_kernel(const int* __restrict__ mask,
                                 float* __restrict__ q,
                                 float* __restrict__ obeta,
                                 float* __restrict__ ok)
{
    int bt = blockIdx.x;
    if (mask[bt] != 0) return;
    int tid = threadIdx.x;
    float4* dst = (float4*)(q + (size_t)bt * 4 * VV);
#pragma unroll 4
    for (int i = tid; i < 32000; i += 256) dst[i] = make_float4(0.f, 0.f, 0.f, 0.f);
    if (tid < 4) {
        obeta[bt * 4 + tid] = 0.f;
        ok[bt * 4 + tid]    = 0.f;
    }
}

// ---------------------------------------------------------------------------
// w2b[j] = dot(W2[j,:], Wb);  w2b[DH] = dot(b2,Wb)+bb
__global__ void w2b_kernel(const float* __restrict__ W2, const float* __restrict__ Wb,
                           const float* __restrict__ b2, const float* __restrict__ bb)
{
    if (blockIdx.x == DH / 8) {
        __shared__ float red[256];
        int tid = threadIdx.x;
        float s = 0.f;
        for (int i = tid; i < DM; i += 256) s += b2[i] * Wb[i];
        red[tid] = s; __syncthreads();
        for (int o = 128; o > 0; o >>= 1) { if (tid < o) red[tid] += red[tid + o]; __syncthreads(); }
        if (tid == 0) g_w2b[DH] = red[0] + bb[0];
        return;
    }
    int w = threadIdx.x >> 5, lane = threadIdx.x & 31;
    int j = blockIdx.x * 8 + w;
    const float* row = W2 + (size_t)j * DM;
    float s = 0.f;
    for (int i = lane; i < DM; i += 32) s += row[i] * Wb[i];
#pragma unroll
    for (int o = 16; o > 0; o >>= 1) s += __shfl_xor_sync(0xffffffffu, s, o);
    if (lane == 0) g_w2b[j] = s;
}

// ---------------------------------------------------------------------------
// Pack Wq[DM][VV] fp32 -> g_Wqh[k2][n] half2 (low = even k)
__global__ void wq_half_kernel(const float* __restrict__ Wq)
{
    int n  = blockIdx.x * 256 + threadIdx.x;   // VV/256 = 125 blocks
    int k2 = blockIdx.y;                       // 512
    float x0 = Wq[(size_t)(2 * k2    ) * VV + n];
    float x1 = Wq[(size_t)(2 * k2 + 1) * VV + n];
    g_Wqh[(size_t)k2 * VV + n] = __floats2half2_rn(x0, x1);
}

// ---------------------------------------------------------------------------
// S = LayerNorm(H + emb[ids] + depth_emb[d]) * g + b  (raw fp32, compacted)
__global__ void s_kernel(const float* __restrict__ H, const int* __restrict__ ids,
                         const float* __restrict__ emb, const float* __restrict__ demb,
                         const float* __restrict__ lng, const float* __restrict__ lnb)
{
    int rp = blockIdx.x;
    if (rp >= g_cnt[0]) return;
    int bt  = g_idx[rp >> 2];
    int d   = rp & 3;
    int tid = threadIdx.x;

    const float* hrow = H    + (size_t)bt * DM;
    const float* erow = emb  + (size_t)ids[bt] * DM;
    const float* drow = demb + (size_t)d * DM;

    float x[4];
    float s = 0.f;
#pragma unroll
    for (int j = 0; j < 4; j++) {
        int i = j * 256 + tid;
        x[j] = hrow[i] + erow[i] + drow[i];
        s += x[j];
    }
    __shared__ float red[256];
    red[tid] = s; __syncthreads();
    for (int o = 128; o > 0; o >>= 1) { if (tid < o) red[tid] += red[tid + o]; __syncthreads(); }
    float mu = red[0] * (1.0f / DM);
    __syncthreads();

    float v = 0.f;
#pragma unroll
    for (int j = 0; j < 4; j++) { float dx = x[j] - mu; v += dx * dx; }
    red[tid] = v; __syncthreads();
    for (int o = 128; o > 0; o >>= 1) { if (tid < o) red[tid] += red[tid + o]; __syncthreads(); }
    float inv = rsqrtf(red[0] * (1.0f / DM) + 1e-5f);

#pragma unroll
    for (int j = 0; j < 4; j++) {
        int i = j * 256 + tid;
        g_S[(size_t)rp * DM + i] = (x[j] - mu) * inv * lng[i] + lnb[i];
    }
}

// ---------------------------------------------------------------------------
// fp32 GEMM geometry (A 128x32 stride 36; B 32x128 stride 136)
#define KCH     32
#define ASTR    36
#define BSTR    136
#define A_TILE_F (128 * ASTR)
#define B_TILE_F (KCH * BSTR)
#define STAGE_F  (A_TILE_F + B_TILE_F)
#define SM_BYTES (2 * STAGE_F * 4)     // 71680

// MODE 0: 3xTF32, O1 = gelu(acc+bias), full K      (G — fp32-exact)
// MODE 2: single TF32, split-K raw partials -> O1  (S2 chunks — q-only path)
template<int MODE>
__global__ void __launch_bounds__(256, 2)
mlp3_kernel(const float* __restrict__ A, const float* __restrict__ W,
            const float* __restrict__ bias,
            float* __restrict__ O1, int N, int K)
{
    const int rowBase = blockIdx.x * 128;
    if (rowBase >= g_cnt[0]) return;
    extern __shared__ float smem[];
    const uint32_t su = smem_u32(smem);
    const int tid     = threadIdx.x;
    const int colBase = blockIdx.y * 128;

    int koff  = 0;
    int niter = K / KCH;
    if (MODE == 2) {
        koff  = blockIdx.z * (K / SPLITK);
        niter = K / SPLITK / KCH;
        O1   += (size_t)blockIdx.z * ROWS * DM;
    }

    const int lane = tid & 31, wid = tid >> 5;
    const int wr = wid >> 1, wc = wid & 1;
    const int g  = lane >> 2, tig = lane & 3;

    float acc[2][8][4];
#pragma unroll
    for (int mt = 0; mt < 2; mt++)
#pragma unroll
        for (int nt = 0; nt < 8; nt++)
#pragma unroll
            for (int k = 0; k < 4; k++) acc[mt][nt][k] = 0.f;

    const float* abase = A + (size_t)rowBase * K + koff;
    const float* bbase = W + (size_t)koff * N + colBase;

    auto load_stage = [&](int s, int c) {
        uint32_t sa = su + (s * STAGE_F) * 4;
        uint32_t sb = su + (s * STAGE_F + A_TILE_F) * 4;
        const float* ag = abase + c * KCH;
        const float* bg = bbase + (size_t)c * KCH * N;
#pragma unroll
        for (int j = 0; j < 4; j++) {
            int idx = tid + 256 * j;
            int row = idx >> 3, seg = idx & 7;
            cp16(sa + (row * ASTR + seg * 4) * 4, ag + (size_t)row * K + seg * 4);
        }
#pragma unroll
        for (int j = 0; j < 4; j++) {
            int idx = tid + 256 * j;
            int row = idx >> 5, seg = idx & 31;
            cp16(sb + (row * BSTR + seg * 4) * 4, bg + (size_t)row * N + seg * 4);
        }
    };

    load_stage(0, 0);
    CP_COMMIT();

    for (int it = 0; it < niter; it++) {
        int s = it & 1;
        CP_WAIT0();
        __syncthreads();
        if (it + 1 < niter) { load_stage(1 - s, it + 1); CP_COMMIT(); }

        const float* As = smem + s * STAGE_F;
        const float* Bs = smem + s * STAGE_F + A_TILE_F;

#pragma unroll
        for (int k8 = 0; k8 < 4; k8++) {
            int kb = k8 * 8;
            uint32_t ah[2][4], al[2][4];
#pragma unroll
            for (int mt = 0; mt < 2; mt++) {
                int m0 = wr * 32 + mt * 16;
                if (MODE == 0) {
                    split2(As[(m0 + g    ) * ASTR + kb + tig    ], ah[mt][0], al[mt][0]);
                    split2(As[(m0 + g + 8) * ASTR + kb + tig    ], ah[mt][1], al[mt][1]);
                    split2(As[(m0 + g    ) * ASTR + kb + tig + 4], ah[mt][2], al[mt][2]);
                    split2(As[(m0 + g + 8) * ASTR + kb + tig + 4], ah[mt][3], al[mt][3]);
                } else {
                    ah[mt][0] = __float_as_uint(rna_tf32(As[(m0 + g    ) * ASTR + kb + tig    ]));
                    ah[mt][1] = __float_as_uint(rna_tf32(As[(m0 + g + 8) * ASTR + kb + tig    ]));
                    ah[mt][2] = __float_as_uint(rna_tf32(As[(m0 + g    ) * ASTR + kb + tig + 4]));
                    ah[mt][3] = __float_as_uint(rna_tf32(As[(m0 + g + 8) * ASTR + kb + tig + 4]));
                }
            }
            uint32_t bh[8][2], bl[8][2];
#pragma unroll
            for (int nt = 0; nt < 8; nt++) {
                int n0 = wc * 64 + nt * 8;
                if (MODE == 0) {
                    split2(Bs[(kb + tig    ) * BSTR + n0 + g], bh[nt][0], bl[nt][0]);
                    split2(Bs[(kb + tig + 4) * BSTR + n0 + g], bh[nt][1], bl[nt][1]);
                } else {
                    bh[nt][0] = __float_as_uint(rna_tf32(Bs[(kb + tig    ) * BSTR + n0 + g]));
                    bh[nt][1] = __float_as_uint(rna_tf32(Bs[(kb + tig + 4) * BSTR + n0 + g]));
                }
            }
#pragma unroll
            for (int mt = 0; mt < 2; mt++)
#pragma unroll
                for (int nt = 0; nt < 8; nt++) {
                    mma_tf32_16x8x8(acc[mt][nt], ah[mt], bh[nt]);
                    if (MODE == 0) {
                        mma_tf32_16x8x8(acc[mt][nt], ah[mt], bl[nt]);
                        mma_tf32_16x8x8(acc[mt][nt], al[mt], bh[nt]);
                    }
                }
        }
        __syncthreads();
    }

#pragma unroll
    for (int mt = 0; mt < 2; mt++) {
        int rb = rowBase + wr * 32 + mt * 16;
        int r0 = rb + g, r1 = rb + g + 8;
#pragma unroll
        for (int nt = 0; nt < 8; nt++) {
            int c = colBase + wc * 64 + nt * 8 + tig * 2;
            if (MODE == 2) {
                *(float2*)&O1[(size_t)r0 * N + c] =
                    make_float2(acc[mt][nt][0], acc[mt][nt][1]);
                *(float2*)&O1[(size_t)r1 * N + c] =
                    make_float2(acc[mt][nt][2], acc[mt][nt][3]);
            } else {
                float b0 = bias[c], b1v = bias[c + 1];
                float v00 = acc[mt][nt][0] + b0, v01 = acc[mt][nt][1] + b1v;
                float v10 = acc[mt][nt][2] + b0, v11 = acc[mt][nt][3] + b1v;
                v00 = 0.5f * v00 * (1.0f + erff(v00 * 0.70710678118654752f));
                v01 = 0.5f * v01 * (1.0f + erff(v01 * 0.70710678118654752f));
                v10 = 0.5f * v10 * (1.0f + erff(v10 * 0.70710678118654752f));
                v11 = 0.5f * v11 * (1.0f + erff(v11 * 0.70710678118654752f));
                *(float2*)&O1[(size_t)r0 * N + c] = make_float2(v00, v01);
                *(float2*)&O1[(size_t)r1 * N + c] = make_float2(v10, v11);
            }
        }
    }
}

// ---------------------------------------------------------------------------
// Reduce split-K partials: S2h = half(sum + bias)
__global__ void reduce_s2h_kernel(const float* __restrict__ b2)
{
    int i4 = blockIdx.x * 256 + threadIdx.x;
    int row = i4 >> 8;
    if (row >= g_cnt[0]) return;
    size_t i = (size_t)i4 * 4;
    const float4 p0 = *(const float4*)&g_P[i];
    const float4 p1 = *(const float4*)&g_P[(size_t)ROWS * DM + i];
    const float4 p2 = *(const float4*)&g_P[2 * (size_t)ROWS * DM + i];
    const float4 p3 = *(const float4*)&g_P[3 * (size_t)ROWS * DM + i];
    int c = (i4 & 255) * 4;
    float4 bv = *(const float4*)&b2[c];
    float vx = ((p0.x + p1.x) + (p2.x + p3.x)) + bv.x;
    float vy = ((p0.y + p1.y) + (p2.y + p3.y)) + bv.y;
    float vz = ((p0.z + p1.z) + (p2.z + p3.z)) + bv.z;
    float vw = ((p0.w + p1.w) + (p2.w + p3.w)) + bv.w;
    __half2* dst = (__half2*)&g_S2h[i];
    dst[0] = __floats2half2_rn(vx, vy);
    dst[1] = __floats2half2_rn(vz, vw);
}

// ---------------------------------------------------------------------------
// fp16 logits GEMM: q = scatter(S2h @ Wqh + bq)
// A smem: [128 m][20 half2 pad] (data 16).  B smem: [16 k2][136 half2 pad] (data 128).
#define ASTR2     20
#define BSTR2     136
#define A_TILE_H2 (128 * ASTR2)            // 2560
#define B_TILE_H2 (16 * BSTR2)             // 2176
#define STAGE_H2  (A_TILE_H2 + B_TILE_H2)  // 4736
#define SMH_BYTES (2 * STAGE_H2 * 4)       // 37888

__global__ void __launch_bounds__(256, 2)
logits_kernel(const __half* __restrict__ Ah, const __half2* __restrict__ Bh2,
              const float* __restrict__ bq, float* __restrict__ q)
{
    const int nv4     = g_cnt[0];
    const int rowBase = blockIdx.x * 128;
    if (rowBase >= nv4) return;
    extern __shared__ uint32_t smh[];
    const uint32_t su = smem_u32(smh);
    const int tid     = threadIdx.x;
    const int colBase = blockIdx.y * 128;

    const int lane = tid & 31, wid = tid >> 5;
    const int wr = wid >> 1, wc = wid & 1;
    const int g  = lane >> 2, tig = lane & 3;

    float acc[2][8][4];
#pragma unroll
    for (int mt = 0; mt < 2; mt++)
#pragma unroll
        for (int nt = 0; nt < 8; nt++)
#pragma unroll
            for (int k = 0; k < 4; k++) acc[mt][nt][k] = 0.f;

    const __half*  abase = Ah + (size_t)rowBase * DM;
    const __half2* bbase = Bh2 + colBase;

    auto load_stage = [&](int s, int c) {
        uint32_t sa = su + (s * STAGE_H2) * 4;
        uint32_t sb = su + (s * STAGE_H2 + A_TILE_H2) * 4;
#pragma unroll
        for (int j = 0; j < 2; j++) {            // A: 512 segs of 16B
            int idx = tid + 256 * j;
            int row = idx >> 2, seg = idx & 3;
            cp16(sa + (row * ASTR2 + seg * 4) * 4,
                 abase + (size_t)row * DM + c * KCH + seg * 8);
        }
#pragma unroll
        for (int j = 0; j < 2; j++) {            // B: 512 segs of 16B
            int idx = tid + 256 * j;
            int k2r = idx >> 5, seg = idx & 31;
            cp16(sb + (k2r * BSTR2 + seg * 4) * 4,
                 bbase + (size_t)(c * 16 + k2r) * VV + seg * 4);
        }
    };

    load_stage(0, 0);
    CP_COMMIT();

    const int NITERL = DM / KCH;
    for (int it = 0; it < NITERL; it++) {
        int st = it & 1;
        CP_WAIT0();
        __syncthreads();
        if (it + 1 < NITERL) { load_stage(1 - st, it + 1); CP_COMMIT(); }

        const uint32_t* As = smh + st * STAGE_H2;
        const uint32_t* Bs = As + A_TILE_H2;

#pragma unroll
        for (int s = 0; s < 2; s++) {            // two k16 steps per KCH=32
            int s8 = s * 8;
            uint32_t a[2][4];
#pragma unroll
            for (int mt = 0; mt < 2; mt++) {
                int m0 = wr * 32 + mt * 16;
                a[mt][0] = As[(m0 + g    ) * ASTR2 + s8 + tig    ];
                a[mt][1] = As[(m0 + g + 8) * ASTR2 + s8 + tig    ];
                a[mt][2] = As[(m0 + g    ) * ASTR2 + s8 + tig + 4];
                a[mt][3] = As[(m0 + g + 8) * ASTR2 + s8 + tig + 4];
            }
            uint32_t b[8][2];
#pragma unroll
            for (int nt = 0; nt < 8; nt++) {
                int n0 = wc * 64 + nt * 8;
                b[nt][0] = Bs[(s8 + tig    ) * BSTR2 + n0 + g];
                b[nt][1] = Bs[(s8 + tig + 4) * BSTR2 + n0 + g];
            }
#pragma unroll
            for (int mt = 0; mt < 2; mt++)
#pragma unroll
                for (int nt = 0; nt < 8; nt++)
                    mma_f16_16x8x16(acc[mt][nt], a[mt], b[nt]);
        }
        __syncthreads();
    }

#pragma unroll
    for (int mt = 0; mt < 2; mt++) {
        int rb  = rowBase + wr * 32 + mt * 16;
        int rc0 = rb + g, rc1 = rb + g + 8;
        int or0 = 0, or1 = 0;
        bool ok0 = rc0 < nv4, ok1 = rc1 < nv4;
        if (ok0) or0 = g_idx[rc0 >> 2] * 4 + (rc0 & 3);
        if (ok1) or1 = g_idx[rc1 >> 2] * 4 + (rc1 & 3);
#pragma unroll
        for (int nt = 0; nt < 8; nt++) {
            int c = colBase + wc * 64 + nt * 8 + tig * 2;
            float bq0 = bq[c], bq1 = bq[c + 1];
            if (ok0)
                *(float2*)&q[(size_t)or0 * VV + c] =
                    make_float2(acc[mt][nt][0] + bq0, acc[mt][nt][1] + bq1);
            if (ok1)
                *(float2*)&q[(size_t)or1 * VV + c] =
                    make_float2(acc[mt][nt][2] + bq0, acc[mt][nt][3] + bq1);
        }
    }
}

// ---------------------------------------------------------------------------
// beta = G @ w2b + cb  (fp32-exact path, independent of S2)
__global__ void beta_kernel(float* __restrict__ obeta, float* __restrict__ ok)
{
    int rp = blockIdx.x;
    if (rp >= g_cnt[0]) return;
    int tid = threadIdx.x;
    const float* row = g_G + (size_t)rp * DH;
    float s = 0.f;
    for (int i = tid; i < DH; i += 256) s += row[i] * g_w2b[i];
    __shared__ float red[256];
    red[tid] = s; __syncthreads();
    for (int o = 128; o > 0; o >>= 1) { if (tid < o) red[tid] += red[tid + o]; __syncthreads(); }
    if (tid == 0) {
        float be = red[0] + g_w2b[DH];
        int orow = g_idx[rp >> 2] * 4 + (rp & 3);
        obeta[orow]  = be;
        g_beta[orow] = be;
        float sig = 1.f / (1.f + expf(-be));
        int k = (int)ceilf(sig * 8.f);
        k = max(1, min(8, k));
        if (sig < 0.25f) k = 0;
        ok[orow] = (float)k;
    }
}

// ---------------------------------------------------------------------------
__global__ void nll_kernel(const float* __restrict__ q, const int* __restrict__ mask,
                           const int* __restrict__ labels)
{
    int r  = blockIdx.x;
    int d  = r & 3;
    int bt = r >> 2;
    int t  = bt % TT;
    int b  = bt / TT;
    int td = t + d + 1;
    bool valid = (td < TT) && (mask[bt] != 0) && (mask[b * TT + td] != 0);
    if (!valid) return;
    int tgt = labels[b * TT + td];

    const float* row = q + (size_t)r * VV;
    int tid = threadIdx.x;
    __shared__ float red[256];

    float mx = -INFINITY;
    for (int i = tid; i < VV; i += 256) mx = fmaxf(mx, row[i]);
    red[tid] = mx; __syncthreads();
    for (int o = 128; o > 0; o >>= 1) { if (tid < o) red[tid] = fmaxf(red[tid], red[tid + o]); __syncthreads(); }
    mx = red[0]; __syncthreads();

    float se = 0.f;
    for (int i = tid; i < VV; i += 256) se += expf(row[i] - mx);
    red[tid] = se; __syncthreads();
    for (int o = 128; o > 0; o >>= 1) { if (tid < o) red[tid] += red[tid + o]; __syncthreads(); }

    if (tid == 0) {
        float nll = logf(red[0]) + mx - row[tgt];
        atomicAdd(&g_acc[0], (double)nll);
        atomicAdd(&g_acc[1], 1.0);
    }
}

// ---------------------------------------------------------------------------
__global__ void bce_kernel(const int* __restrict__ mask)
{
    int idx = blockIdx.x * 256 + threadIdx.x;
    if (idx >= BTN) return;
    int t = idx % TT;
    int b = idx / TT;
    if (mask[idx] == 0) return;
    float bsum = 0.f;
    bool anyv = false;
#pragma unroll
    for (int d = 0; d < 4; d++) {
        int td = t + d + 1;
        bool valid = (td < TT) && (mask[b * TT + td] != 0);
        float be  = g_beta[idx * 4 + d];
        float bce = fmaxf(be, 0.f) + log1pf(expf(-fabsf(be))) - (valid ? be : 0.f);
        bsum += bce;
        anyv |= valid;
    }
    if (anyv) {
        atomicAdd(&g_acc[2], (double)bsum);
        atomicAdd(&g_acc[3], 1.0);
    }
}

// ---------------------------------------------------------------------------
__global__ void fin_kernel(float* __restrict__ oloss)
{
    double cnt = g_acc[1];
    double Lq  = (cnt > 0.0) ? g_acc[0] / cnt : 0.0;
    double den = g_acc[3]; if (den < 1.0) den = 1.0;
    double Lb  = g_acc[2] / den;
    oloss[0] = (float)(Lq + Lb);
}

// ---------------------------------------------------------------------------
extern "C" void kernel_launch(void* const* d_in, const int* in_sizes, int n_in,
                              void* d_out, int out_size)
{
    const float* H      = (const float*)d_in[0];
    const int*   ids    = (const int*)  d_in[1];
    const int*   mask   = (const int*)  d_in[2];
    const int*   labels = (const int*)  d_in[3];
    const float* emb    = (const float*)d_in[4];
    const float* demb   = (const float*)d_in[5];
    const float* ln_g   = (const float*)d_in[6];
    const float* ln_b   = (const float*)d_in[7];
    const float* W1     = (const float*)d_in[8];
    const float* b1     = (const float*)d_in[9];
    const float* W2     = (const float*)d_in[10];
    const float* b2     = (const float*)d_in[11];
    const float* Wq     = (const float*)d_in[12];
    const float* bq     = (const float*)d_in[13];
    const float* Wb     = (const float*)d_in[14];
    const float* bb     = (const float*)d_in[15];

    float* out   = (float*)d_out;
    float* q     = out;
    float* obeta = out + (size_t)ROWS * VV;
    float* ok    = obeta + ROWS;
    float* oloss = ok + ROWS;

    void *pS, *pG, *pP, *pS2h, *pWqh;
    cudaGetSymbolAddress(&pS,   g_S);
    cudaGetSymbolAddress(&pG,   g_G);
    cudaGetSymbolAddress(&pP,   g_P);
    cudaGetSymbolAddress(&pS2h, g_S2h);
    cudaGetSymbolAddress(&pWqh, g_Wqh);

    cudaFuncSetAttribute(logits_kernel,
                         cudaFuncAttributeMaxDynamicSharedMemorySize, SMH_BYTES);
    cudaFuncSetAttribute(mlp3_kernel<0>,
                         cudaFuncAttributeMaxDynamicSharedMemorySize, SM_BYTES);
    cudaFuncSetAttribute(mlp3_kernel<2>,
                         cudaFuncAttributeMaxDynamicSharedMemorySize, SM_BYTES);

    zero_acc_kernel<<<1, 32>>>();
    compact_kernel<<<1, BTN>>>(mask);
    zero_fill_kernel<<<BTN, 256>>>(mask, q, obeta, ok);

    w2b_kernel<<<DH / 8 + 1, 256>>>(W2, Wb, b2, bb);
    wq_half_kernel<<<dim3(VV / 256, DM / 2), 256>>>(Wq);

    s_kernel<<<ROWS, 256>>>(H, ids, emb, demb, ln_g, ln_b);

    // G = gelu(S @ W1 + b1) — fp32-exact (3xTF32)
    mlp3_kernel<0><<<dim3(ROWS / 128, DH / 128), 256, SM_BYTES>>>(
        (const float*)pS, W1, b1, (float*)pG, DH, DM);

    // beta from exact G (independent of S2 precision)
    beta_kernel<<<ROWS, 256>>>(obeta, ok);

    // S2 partials — single tf32 (feeds only q)
    mlp3_kernel<2><<<dim3(ROWS / 128, DM / 128, SPLITK), 256, SM_BYTES>>>(
        (const float*)pG, W2, nullptr, (float*)pP, DM, DH);

    reduce_s2h_kernel<<<ROWS * DM / 1024, 256>>>(b2);

    // q = scatter(S2h @ Wqh + bq) — fp16 HMMA
    logits_kernel<<<dim3(ROWS / 128, VV / 128), 256, SMH_BYTES>>>(
        (const __half*)pS2h, (const __half2*)pWqh, bq, q);

    nll_kernel<<<ROWS, 256>>>(q, mask, labels);
    bce_kernel<<<(BTN + 255) / 256, 256>>>(mask);
    fin_kernel<<<1, 1>>>(oloss);

    (void)in_sizes; (void)n_in; (void)out_size;
}

// round 9
// speedup vs baseline: 2.0165x; 1.2337x over previous
#include <cuda_runtime.h>
#include <cuda_fp16.h>
#include <math.h>
#include <stdint.h>

// Problem constants
#define BB   2
#define TT   512
#define DM   1024
#define DH   4096
#define DD   4
#define VV   32000
#define ROWS (BB*TT*DD)   // 4096
#define BTN  (BB*TT)      // 1024
#define SPLITK 4

// Scratch (static device globals — no allocation allowed)
__device__ __half  g_Shi[ROWS*DM];         // LN output hi (fp16 split)
__device__ __half  g_Slo[ROWS*DM];         // LN output lo
__device__ __half2 g_W1h[(DM/2)*DH];       // W1 hi packed [k/2][n]
__device__ __half2 g_W1l[(DM/2)*DH];       // W1 lo packed
__device__ __half2 g_W2h[(DH/2)*DM];       // W2 hi packed [k/2][n]
__device__ float   g_G  [ROWS*DH];         // gelu(MLP hidden), fp32-exact (beta)
__device__ __half  g_Gh [ROWS*DH];         // gelu(MLP hidden), fp16 (q path)
__device__ float   g_P  [SPLITK*ROWS*DM];  // split-K partials for S2
__device__ __half  g_S2h[ROWS*DM];         // fp16 S2
__device__ __half2 g_Wqh[(DM/2)*VV];       // Wq packed [k/2][n]
__device__ float   g_w2b[DH+1];            // W2@Wb (+ cb in last slot)
__device__ float   g_beta[ROWS];
__device__ int     g_idx [BTN];
__device__ int     g_cnt [1];
__device__ double  g_acc[4];

// ============================================================================
__device__ __forceinline__ uint32_t smem_u32(const void* p) {
    uint32_t a;
    asm("{ .reg .u64 t; cvta.to.shared.u64 t, %1; cvt.u32.u64 %0, t; }"
        : "=r"(a) : "l"(p));
    return a;
}
__device__ __forceinline__ void cp16(uint32_t s, const void* g) {
    asm volatile("cp.async.cg.shared.global [%0], [%1], 16;" :: "r"(s), "l"(g));
}
#define CP_COMMIT() asm volatile("cp.async.commit_group;" ::: "memory")
#define CP_WAIT0()  asm volatile("cp.async.wait_group 0;" ::: "memory")

__device__ __forceinline__ void mma_f16_16x8x16(float* d, const uint32_t* a,
                                                const uint32_t* b) {
    asm volatile(
        "mma.sync.aligned.m16n8k16.row.col.f32.f16.f16.f32 "
        "{%0,%1,%2,%3}, {%4,%5,%6,%7}, {%8,%9}, {%0,%1,%2,%3};"
        : "+f"(d[0]), "+f"(d[1]), "+f"(d[2]), "+f"(d[3])
        : "r"(a[0]), "r"(a[1]), "r"(a[2]), "r"(a[3]), "r"(b[0]), "r"(b[1]));
}

// ============================================================================
__global__ void zero_acc_kernel() {
    if (threadIdx.x < 4) g_acc[threadIdx.x] = 0.0;
}

// ---------------------------------------------------------------------------
__global__ void compact_kernel(const int* __restrict__ mask) {
    __shared__ int pre[BTN];
    int tid = threadIdx.x;
    int m = (mask[tid] != 0) ? 1 : 0;
    pre[tid] = m;
    __syncthreads();
    for (int o = 1; o < BTN; o <<= 1) {
        int v = (tid >= o) ? pre[tid - o] : 0;
        __syncthreads();
        pre[tid] += v;
        __syncthreads();
    }
    int mv = pre[BTN - 1];
    if (m) g_idx[pre[tid] - 1] = tid;
    if (tid >= mv) g_idx[tid] = 0;
    if (tid == 0) g_cnt[0] = mv * 4;
}

// ---------------------------------------------------------------------------
__global__ void zero_fill_kernel(const int* __restrict__ mask,
                                 float* __restrict__ q,
                                 float* __restrict__ obeta,
                                 float* __restrict__ ok)
{
    int bt = blockIdx.x;
    if (mask[bt] != 0) return;
    int tid = threadIdx.x;
    float4* dst = (float4*)(q + (size_t)bt * 4 * VV);
#pragma unroll 4
    for (int i = tid; i < 32000; i += 256) dst[i] = make_float4(0.f, 0.f, 0.f, 0.f);
    if (tid < 4) {
        obeta[bt * 4 + tid] = 0.f;
        ok[bt * 4 + tid]    = 0.f;
    }
}

// ---------------------------------------------------------------------------
// w2b[j] = dot(W2[j,:], Wb);  w2b[DH] = dot(b2,Wb)+bb
__global__ void w2b_kernel(const float* __restrict__ W2, const float* __restrict__ Wb,
                           const float* __restrict__ b2, const float* __restrict__ bb)
{
    if (blockIdx.x == DH / 8) {
        __shared__ float red[256];
        int tid = threadIdx.x;
        float s = 0.f;
        for (int i = tid; i < DM; i += 256) s += b2[i] * Wb[i];
        red[tid] = s; __syncthreads();
        for (int o = 128; o > 0; o >>= 1) { if (tid < o) red[tid] += red[tid + o]; __syncthreads(); }
        if (tid == 0) g_w2b[DH] = red[0] + bb[0];
        return;
    }
    int w = threadIdx.x >> 5, lane = threadIdx.x & 31;
    int j = blockIdx.x * 8 + w;
    const float* row = W2 + (size_t)j * DM;
    float s = 0.f;
    for (int i = lane; i < DM; i += 32) s += row[i] * Wb[i];
#pragma unroll
    for (int o = 16; o > 0; o >>= 1) s += __shfl_xor_sync(0xffffffffu, s, o);
    if (lane == 0) g_w2b[j] = s;
}

// ---------------------------------------------------------------------------
// Pack fp32 [K][N] -> half2 [k/2][n], optional lo array (fp16 split residual)
__global__ void packw_kernel(const float* __restrict__ W,
                             __half2* __restrict__ Dh, __half2* __restrict__ Dl,
                             int N)
{
    int n  = blockIdx.x * 256 + threadIdx.x;
    int k2 = blockIdx.y;
    float x0 = W[(size_t)(2 * k2    ) * N + n];
    float x1 = W[(size_t)(2 * k2 + 1) * N + n];
    __half h0 = __float2half_rn(x0), h1 = __float2half_rn(x1);
    Dh[(size_t)k2 * N + n] = __halves2half2(h0, h1);
    if (Dl)
        Dl[(size_t)k2 * N + n] = __halves2half2(
            __float2half_rn(x0 - __half2float(h0)),
            __float2half_rn(x1 - __half2float(h1)));
}

// ---------------------------------------------------------------------------
// S = LayerNorm(H + emb + depth_emb) * g + b  -> fp16 hi/lo (compacted rows)
__global__ void s_kernel(const float* __restrict__ H, const int* __restrict__ ids,
                         const float* __restrict__ emb, const float* __restrict__ demb,
                         const float* __restrict__ lng, const float* __restrict__ lnb)
{
    int rp = blockIdx.x;
    if (rp >= g_cnt[0]) return;
    int bt  = g_idx[rp >> 2];
    int d   = rp & 3;
    int tid = threadIdx.x;

    const float* hrow = H    + (size_t)bt * DM;
    const float* erow = emb  + (size_t)ids[bt] * DM;
    const float* drow = demb + (size_t)d * DM;

    float x[4];
    float s = 0.f;
#pragma unroll
    for (int j = 0; j < 4; j++) {
        int i = j * 256 + tid;
        x[j] = hrow[i] + erow[i] + drow[i];
        s += x[j];
    }
    __shared__ float red[256];
    red[tid] = s; __syncthreads();
    for (int o = 128; o > 0; o >>= 1) { if (tid < o) red[tid] += red[tid + o]; __syncthreads(); }
    float mu = red[0] * (1.0f / DM);
    __syncthreads();

    float v = 0.f;
#pragma unroll
    for (int j = 0; j < 4; j++) { float dx = x[j] - mu; v += dx * dx; }
    red[tid] = v; __syncthreads();
    for (int o = 128; o > 0; o >>= 1) { if (tid < o) red[tid] += red[tid + o]; __syncthreads(); }
    float inv = rsqrtf(red[0] * (1.0f / DM) + 1e-5f);

#pragma unroll
    for (int j = 0; j < 4; j++) {
        int i = j * 256 + tid;
        float val = (x[j] - mu) * inv * lng[i] + lnb[i];
        __half h  = __float2half_rn(val);
        g_Shi[(size_t)rp * DM + i] = h;
        g_Slo[(size_t)rp * DM + i] = __float2half_rn(val - __half2float(h));
    }
}

// ---------------------------------------------------------------------------
// fp16 GEMM geometry (half2 units): A [128 m][20 pad] (16 data), B [16 k2][136 pad] (128 data)
#define KCH       32
#define ASTR2     20
#define BSTR2     136
#define A_TILE_H2 (128 * ASTR2)            // 2560
#define B_TILE_H2 (16 * BSTR2)             // 2176

// ---------------------------------------------------------------------------
// Unified fp16 GEMM on compacted rows.
// MODE 0: 2xFP16-split (3 HMMA passes), epilogue gelu -> g_G fp32 + g_Gh half.
// MODE 2: single pass, split-K raw partials -> O1 fp32.
// MODE 3: single pass (logits), scatter epilogue with bias -> O1 fp32 (q).
template<int MODE>
__global__ void __launch_bounds__(256, 2)
mlp_h_kernel(const __half* __restrict__ Ah, const __half* __restrict__ Al,
             const __half2* __restrict__ Bh, const __half2* __restrict__ Bl,
             const float* __restrict__ bias,
             float* __restrict__ O1, __half* __restrict__ Oh,
             int N, int K)
{
    constexpr int NARR  = (MODE == 0) ? 2 : 1;
    constexpr int STG   = NARR * (A_TILE_H2 + B_TILE_H2);

    const int nv4     = g_cnt[0];
    const int rowBase = blockIdx.x * 128;
    if (rowBase >= nv4) return;
    extern __shared__ uint32_t smh[];
    const uint32_t su = smem_u32(smh);
    const int tid     = threadIdx.x;
    const int colBase = blockIdx.y * 128;

    int koff  = 0;
    int niter = K / KCH;
    if (MODE == 2) {
        koff  = blockIdx.z * (K / SPLITK);
        niter = K / SPLITK / KCH;
        O1   += (size_t)blockIdx.z * ROWS * DM;
    }

    const int lane = tid & 31, wid = tid >> 5;
    const int wr = wid >> 1, wc = wid & 1;
    const int g  = lane >> 2, tig = lane & 3;

    float acc[2][8][4];
#pragma unroll
    for (int mt = 0; mt < 2; mt++)
#pragma unroll
        for (int nt = 0; nt < 8; nt++)
#pragma unroll
            for (int k = 0; k < 4; k++) acc[mt][nt][k] = 0.f;

    const __half*  a0 = Ah + (size_t)rowBase * K + koff;
    const __half*  a1 = (NARR == 2) ? (Al + (size_t)rowBase * K + koff) : a0;
    const __half2* b0 = Bh + (size_t)(koff / 2) * N + colBase;
    const __half2* b1 = (NARR == 2) ? (Bl + (size_t)(koff / 2) * N + colBase) : b0;

    auto load_stage = [&](int s, int c) {
        const __half*  ap[2] = { a0, a1 };
        const __half2* bp[2] = { b0, b1 };
#pragma unroll
        for (int t = 0; t < NARR; t++) {
            uint32_t sa = su + (s * STG + t * A_TILE_H2) * 4;
            uint32_t sb = su + (s * STG + NARR * A_TILE_H2 + t * B_TILE_H2) * 4;
#pragma unroll
            for (int j = 0; j < 2; j++) {            // A: 512 segs of 16B
                int idx = tid + 256 * j;
                int row = idx >> 2, seg = idx & 3;
                cp16(sa + (row * ASTR2 + seg * 4) * 4,
                     ap[t] + (size_t)row * K + c * KCH + seg * 8);
            }
#pragma unroll
            for (int j = 0; j < 2; j++) {            // B: 512 segs of 16B
                int idx = tid + 256 * j;
                int k2r = idx >> 5, seg = idx & 31;
                cp16(sb + (k2r * BSTR2 + seg * 4) * 4,
                     bp[t] + (size_t)(c * 16 + k2r) * N + seg * 4);
            }
        }
    };

    load_stage(0, 0);
    CP_COMMIT();

    for (int it = 0; it < niter; it++) {
        int st = it & 1;
        CP_WAIT0();
        __syncthreads();
        if (it + 1 < niter) { load_stage(1 - st, it + 1); CP_COMMIT(); }

        const uint32_t* Ash = smh + st * STG;
        const uint32_t* Asl = Ash + A_TILE_H2;                 // valid iff NARR==2
        const uint32_t* Bsh = Ash + NARR * A_TILE_H2;
        const uint32_t* Bsl = Bsh + B_TILE_H2;

#pragma unroll
        for (int s = 0; s < 2; s++) {                // two k16 steps per KCH=32
            int s8 = s * 8;
            uint32_t ah[2][4], al[2][4];
#pragma unroll
            for (int mt = 0; mt < 2; mt++) {
                int m0 = wr * 32 + mt * 16;
                ah[mt][0] = Ash[(m0 + g    ) * ASTR2 + s8 + tig    ];
                ah[mt][1] = Ash[(m0 + g + 8) * ASTR2 + s8 + tig    ];
                ah[mt][2] = Ash[(m0 + g    ) * ASTR2 + s8 + tig + 4];
                ah[mt][3] = Ash[(m0 + g + 8) * ASTR2 + s8 + tig + 4];
                if (MODE == 0) {
                    al[mt][0] = Asl[(m0 + g    ) * ASTR2 + s8 + tig    ];
                    al[mt][1] = Asl[(m0 + g + 8) * ASTR2 + s8 + tig    ];
                    al[mt][2] = Asl[(m0 + g    ) * ASTR2 + s8 + tig + 4];
                    al[mt][3] = Asl[(m0 + g + 8) * ASTR2 + s8 + tig + 4];
                }
            }
            uint32_t bh[8][2], bl[8][2];
#pragma unroll
            for (int nt = 0; nt < 8; nt++) {
                int n0 = wc * 64 + nt * 8;
                bh[nt][0] = Bsh[(s8 + tig    ) * BSTR2 + n0 + g];
                bh[nt][1] = Bsh[(s8 + tig + 4) * BSTR2 + n0 + g];
                if (MODE == 0) {
                    bl[nt][0] = Bsl[(s8 + tig    ) * BSTR2 + n0 + g];
                    bl[nt][1] = Bsl[(s8 + tig + 4) * BSTR2 + n0 + g];
                }
            }
#pragma unroll
            for (int mt = 0; mt < 2; mt++)
#pragma unroll
                for (int nt = 0; nt < 8; nt++) {
                    mma_f16_16x8x16(acc[mt][nt], ah[mt], bh[nt]);
                    if (MODE == 0) {
                        mma_f16_16x8x16(acc[mt][nt], ah[mt], bl[nt]);
                        mma_f16_16x8x16(acc[mt][nt], al[mt], bh[nt]);
                    }
                }
        }
        __syncthreads();
    }

    // Epilogues
#pragma unroll
    for (int mt = 0; mt < 2; mt++) {
        int rb  = rowBase + wr * 32 + mt * 16;
        int rc0 = rb + g, rc1 = rb + g + 8;
        if (MODE == 3) {
            int or0 = 0, or1 = 0;
            bool ok0 = rc0 < nv4, ok1 = rc1 < nv4;
            if (ok0) or0 = g_idx[rc0 >> 2] * 4 + (rc0 & 3);
            if (ok1) or1 = g_idx[rc1 >> 2] * 4 + (rc1 & 3);
#pragma unroll
            for (int nt = 0; nt < 8; nt++) {
                int c = colBase + wc * 64 + nt * 8 + tig * 2;
                float bq0 = bias[c], bq1 = bias[c + 1];
                if (ok0)
                    *(float2*)&O1[(size_t)or0 * N + c] =
                        make_float2(acc[mt][nt][0] + bq0, acc[mt][nt][1] + bq1);
                if (ok1)
                    *(float2*)&O1[(size_t)or1 * N + c] =
                        make_float2(acc[mt][nt][2] + bq0, acc[mt][nt][3] + bq1);
            }
        } else {
#pragma unroll
            for (int nt = 0; nt < 8; nt++) {
                int c = colBase + wc * 64 + nt * 8 + tig * 2;
                if (MODE == 2) {
                    *(float2*)&O1[(size_t)rc0 * N + c] =
                        make_float2(acc[mt][nt][0], acc[mt][nt][1]);
                    *(float2*)&O1[(size_t)rc1 * N + c] =
                        make_float2(acc[mt][nt][2], acc[mt][nt][3]);
                } else {  // MODE 0
                    float b0 = bias[c], b1v = bias[c + 1];
                    float v00 = acc[mt][nt][0] + b0, v01 = acc[mt][nt][1] + b1v;
                    float v10 = acc[mt][nt][2] + b0, v11 = acc[mt][nt][3] + b1v;
                    v00 = 0.5f * v00 * (1.0f + erff(v00 * 0.70710678118654752f));
                    v01 = 0.5f * v01 * (1.0f + erff(v01 * 0.70710678118654752f));
                    v10 = 0.5f * v10 * (1.0f + erff(v10 * 0.70710678118654752f));
                    v11 = 0.5f * v11 * (1.0f + erff(v11 * 0.70710678118654752f));
                    *(float2*)&O1[(size_t)rc0 * N + c] = make_float2(v00, v01);
                    *(float2*)&O1[(size_t)rc1 * N + c] = make_float2(v10, v11);
                    *(__half2*)&Oh[(size_t)rc0 * N + c] = __floats2half2_rn(v00, v01);
                    *(__half2*)&Oh[(size_t)rc1 * N + c] = __floats2half2_rn(v10, v11);
                }
            }
        }
    }
}

// ---------------------------------------------------------------------------
// Reduce split-K partials: S2h = half(sum + bias)
__global__ void reduce_s2h_kernel(const float* __restrict__ b2)
{
    int i4 = blockIdx.x * 256 + threadIdx.x;
    int row = i4 >> 8;
    if (row >= g_cnt[0]) return;
    size_t i = (size_t)i4 * 4;
    const float4 p0 = *(const float4*)&g_P[i];
    const float4 p1 = *(const float4*)&g_P[(size_t)ROWS * DM + i];
    const float4 p2 = *(const float4*)&g_P[2 * (size_t)ROWS * DM + i];
    const float4 p3 = *(const float4*)&g_P[3 * (size_t)ROWS * DM + i];
    int c = (i4 & 255) * 4;
    float4 bv = *(const float4*)&b2[c];
    float vx = ((p0.x + p1.x) + (p2.x + p3.x)) + bv.x;
    float vy = ((p0.y + p1.y) + (p2.y + p3.y)) + bv.y;
    float vz = ((p0.z + p1.z) + (p2.z + p3.z)) + bv.z;
    float vw = ((p0.w + p1.w) + (p2.w + p3.w)) + bv.w;
    __half2* dst = (__half2*)&g_S2h[i];
    dst[0] = __floats2half2_rn(vx, vy);
    dst[1] = __floats2half2_rn(vz, vw);
}

// ---------------------------------------------------------------------------
// beta = G @ w2b + cb  (fp32-exact path)
__global__ void beta_kernel(float* __restrict__ obeta, float* __restrict__ ok)
{
    int rp = blockIdx.x;
    if (rp >= g_cnt[0]) return;
    int tid = threadIdx.x;
    const float* row = g_G + (size_t)rp * DH;
    float s = 0.f;
    for (int i = tid; i < DH; i += 256) s += row[i] * g_w2b[i];
    __shared__ float red[256];
    red[tid] = s; __syncthreads();
    for (int o = 128; o > 0; o >>= 1) { if (tid < o) red[tid] += red[tid + o]; __syncthreads(); }
    if (tid == 0) {
        float be = red[0] + g_w2b[DH];
        int orow = g_idx[rp >> 2] * 4 + (rp & 3);
        obeta[orow]  = be;
        g_beta[orow] = be;
        float sig = 1.f / (1.f + expf(-be));
        int k = (int)ceilf(sig * 8.f);
        k = max(1, min(8, k));
        if (sig < 0.25f) k = 0;
        ok[orow] = (float)k;
    }
}

// ---------------------------------------------------------------------------
__global__ void nll_kernel(const float* __restrict__ q, const int* __restrict__ mask,
                           const int* __restrict__ labels)
{
    int r  = blockIdx.x;
    int d  = r & 3;
    int bt = r >> 2;
    int t  = bt % TT;
    int b  = bt / TT;
    int td = t + d + 1;
    bool valid = (td < TT) && (mask[bt] != 0) && (mask[b * TT + td] != 0);
    if (!valid) return;
    int tgt = labels[b * TT + td];

    const float* row = q + (size_t)r * VV;
    int tid = threadIdx.x;
    __shared__ float red[256];

    float mx = -INFINITY;
    for (int i = tid; i < VV; i += 256) mx = fmaxf(mx, row[i]);
    red[tid] = mx; __syncthreads();
    for (int o = 128; o > 0; o >>= 1) { if (tid < o) red[tid] = fmaxf(red[tid], red[tid + o]); __syncthreads(); }
    mx = red[0]; __syncthreads();

    float se = 0.f;
    for (int i = tid; i < VV; i += 256) se += expf(row[i] - mx);
    red[tid] = se; __syncthreads();
    for (int o = 128; o > 0; o >>= 1) { if (tid < o) red[tid] += red[tid + o]; __syncthreads(); }

    if (tid == 0) {
        float nll = logf(red[0]) + mx - row[tgt];
        atomicAdd(&g_acc[0], (double)nll);
        atomicAdd(&g_acc[1], 1.0);
    }
}

// ---------------------------------------------------------------------------
__global__ void bce_kernel(const int* __restrict__ mask)
{
    int idx = blockIdx.x * 256 + threadIdx.x;
    if (idx >= BTN) return;
    int t = idx % TT;
    int b = idx / TT;
    if (mask[idx] == 0) return;
    float bsum = 0.f;
    bool anyv = false;
#pragma unroll
    for (int d = 0; d < 4; d++) {
        int td = t + d + 1;
        bool valid = (td < TT) && (mask[b * TT + td] != 0);
        float be  = g_beta[idx * 4 + d];
        float bce = fmaxf(be, 0.f) + log1pf(expf(-fabsf(be))) - (valid ? be : 0.f);
        bsum += bce;
        anyv |= valid;
    }
    if (anyv) {
        atomicAdd(&g_acc[2], (double)bsum);
        atomicAdd(&g_acc[3], 1.0);
    }
}

// ---------------------------------------------------------------------------
__global__ void fin_kernel(float* __restrict__ oloss)
{
    double cnt = g_acc[1];
    double Lq  = (cnt > 0.0) ? g_acc[0] / cnt : 0.0;
    double den = g_acc[3]; if (den < 1.0) den = 1.0;
    double Lb  = g_acc[2] / den;
    oloss[0] = (float)(Lq + Lb);
}

// ---------------------------------------------------------------------------
extern "C" void kernel_launch(void* const* d_in, const int* in_sizes, int n_in,
                              void* d_out, int out_size)
{
    const float* H      = (const float*)d_in[0];
    const int*   ids    = (const int*)  d_in[1];
    const int*   mask   = (const int*)  d_in[2];
    const int*   labels = (const int*)  d_in[3];
    const float* emb    = (const float*)d_in[4];
    const float* demb   = (const float*)d_in[5];
    const float* ln_g   = (const float*)d_in[6];
    const float* ln_b   = (const float*)d_in[7];
    const float* W1     = (const float*)d_in[8];
    const float* b1     = (const float*)d_in[9];
    const float* W2     = (const float*)d_in[10];
    const float* b2     = (const float*)d_in[11];
    const float* Wq     = (const float*)d_in[12];
    const float* bq     = (const float*)d_in[13];
    const float* Wb     = (const float*)d_in[14];
    const float* bb     = (const float*)d_in[15];

    float* out   = (float*)d_out;
    float* q     = out;
    float* obeta = out + (size_t)ROWS * VV;
    float* ok    = obeta + ROWS;
    float* oloss = ok + ROWS;

    void *pShi, *pSlo, *pW1h, *pW1l, *pW2h, *pG, *pGh, *pP, *pS2h, *pWqh;
    cudaGetSymbolAddress(&pShi, g_Shi);
    cudaGetSymbolAddress(&pSlo, g_Slo);
    cudaGetSymbolAddress(&pW1h, g_W1h);
    cudaGetSymbolAddress(&pW1l, g_W1l);
    cudaGetSymbolAddress(&pW2h, g_W2h);
    cudaGetSymbolAddress(&pG,   g_G);
    cudaGetSymbolAddress(&pGh,  g_Gh);
    cudaGetSymbolAddress(&pP,   g_P);
    cudaGetSymbolAddress(&pS2h, g_S2h);
    cudaGetSymbolAddress(&pWqh, g_Wqh);

    const int SM0 = 2 * 2 * (A_TILE_H2 + B_TILE_H2) * 4;  // MODE0: 75776
    const int SM1 = 2 * 1 * (A_TILE_H2 + B_TILE_H2) * 4;  // MODE2/3: 37888
    cudaFuncSetAttribute(mlp_h_kernel<0>,
                         cudaFuncAttributeMaxDynamicSharedMemorySize, SM0);
    cudaFuncSetAttribute(mlp_h_kernel<2>,
                         cudaFuncAttributeMaxDynamicSharedMemorySize, SM1);
    cudaFuncSetAttribute(mlp_h_kernel<3>,
                         cudaFuncAttributeMaxDynamicSharedMemorySize, SM1);

    zero_acc_kernel<<<1, 32>>>();
    compact_kernel<<<1, BTN>>>(mask);
    zero_fill_kernel<<<BTN, 256>>>(mask, q, obeta, ok);

    w2b_kernel<<<DH / 8 + 1, 256>>>(W2, Wb, b2, bb);
    packw_kernel<<<dim3(VV / 256, DM / 2), 256>>>(Wq, (__half2*)pWqh, nullptr, VV);
    packw_kernel<<<dim3(DH / 256, DM / 2), 256>>>(W1, (__half2*)pW1h, (__half2*)pW1l, DH);
    packw_kernel<<<dim3(DM / 256, DH / 2), 256>>>(W2, (__half2*)pW2h, nullptr, DM);

    s_kernel<<<ROWS, 256>>>(H, ids, emb, demb, ln_g, ln_b);

    // G = gelu(S @ W1 + b1) — 2xFP16-split (3 HMMA), fp32 + fp16 outputs
    mlp_h_kernel<0><<<dim3(ROWS / 128, DH / 128), 256, SM0>>>(
        (const __half*)pShi, (const __half*)pSlo,
        (const __half2*)pW1h, (const __half2*)pW1l,
        b1, (float*)pG, (__half*)pGh, DH, DM);

    // beta from fp32-exact G
    beta_kernel<<<ROWS, 256>>>(obeta, ok);

    // S2 partials — single fp16 pass, split-K
    mlp_h_kernel<2><<<dim3(ROWS / 128, DM / 128, SPLITK), 256, SM1>>>(
        (const __half*)pGh, nullptr, (const __half2*)pW2h, nullptr,
        nullptr, (float*)pP, nullptr, DM, DH);

    reduce_s2h_kernel<<<ROWS * DM / 1024, 256>>>(b2);

    // q = scatter(S2h @ Wqh + bq) — fp16 HMMA
    mlp_h_kernel<3><<<dim3(ROWS / 128, VV / 128), 256, SM1>>>(
        (const __half*)pS2h, nullptr, (const __half2*)pWqh, nullptr,
        bq, q, nullptr, VV, DM);

    nll_kernel<<<ROWS, 256>>>(q, mask, labels);
    bce_kernel<<<(BTN + 255) / 256, 256>>>(mask);
    fin_kernel<<<1, 1>>>(oloss);

    (void)in_sizes; (void)n_in; (void)out_size;
}

// round 10
// speedup vs baseline: 2.1741x; 1.0781x over previous
#include <cuda_runtime.h>
#include <cuda_fp16.h>
#include <math.h>
#include <stdint.h>

// Problem constants
#define BB   2
#define TT   512
#define DM   1024
#define DH   4096
#define DD   4
#define VV   32000
#define ROWS (BB*TT*DD)   // 4096
#define BTN  (BB*TT)      // 1024
#define SPLITK 4
#define LSEC  (2 * (VV / 128))   // 500 LSE partials per row

// Scratch (static device globals — no allocation allowed)
__device__ __half  g_Shi[ROWS*DM];
__device__ __half  g_Slo[ROWS*DM];
__device__ __half2 g_W1h[(DM/2)*DH];
__device__ __half2 g_W1l[(DM/2)*DH];
__device__ __half2 g_W2h[(DH/2)*DM];
__device__ float   g_G  [ROWS*DH];         // fp32-exact gelu (beta path)
__device__ __half  g_Gh [ROWS*DH];         // fp16 gelu (q path)
__device__ float   g_P  [SPLITK*ROWS*DM];
__device__ __half  g_S2h[ROWS*DM];
__device__ __half2 g_Wqh[(DM/2)*VV];
__device__ float   g_w2b[DH+1];
__device__ float   g_beta[ROWS];
__device__ float2  g_lse[(size_t)ROWS*LSEC];  // (max, sumexp) partials
__device__ int     g_idx [BTN];
__device__ int     g_cnt [1];
__device__ double  g_acc[4];

// ============================================================================
__device__ __forceinline__ uint32_t smem_u32(const void* p) {
    uint32_t a;
    asm("{ .reg .u64 t; cvta.to.shared.u64 t, %1; cvt.u32.u64 %0, t; }"
        : "=r"(a) : "l"(p));
    return a;
}
__device__ __forceinline__ void cp16(uint32_t s, const void* g) {
    asm volatile("cp.async.cg.shared.global [%0], [%1], 16;" :: "r"(s), "l"(g));
}
#define CP_COMMIT() asm volatile("cp.async.commit_group;" ::: "memory")
#define CP_WAIT0()  asm volatile("cp.async.wait_group 0;" ::: "memory")

__device__ __forceinline__ void mma_f16_16x8x16(float* d, const uint32_t* a,
                                                const uint32_t* b) {
    asm volatile(
        "mma.sync.aligned.m16n8k16.row.col.f32.f16.f16.f32 "
        "{%0,%1,%2,%3}, {%4,%5,%6,%7}, {%8,%9}, {%0,%1,%2,%3};"
        : "+f"(d[0]), "+f"(d[1]), "+f"(d[2]), "+f"(d[3])
        : "r"(a[0]), "r"(a[1]), "r"(a[2]), "r"(a[3]), "r"(b[0]), "r"(b[1]));
}

// ============================================================================
// compact + zero g_acc
__global__ void compact_kernel(const int* __restrict__ mask) {
    __shared__ int pre[BTN];
    int tid = threadIdx.x;
    if (tid < 4) g_acc[tid] = 0.0;
    int m = (mask[tid] != 0) ? 1 : 0;
    pre[tid] = m;
    __syncthreads();
    for (int o = 1; o < BTN; o <<= 1) {
        int v = (tid >= o) ? pre[tid - o] : 0;
        __syncthreads();
        pre[tid] += v;
        __syncthreads();
    }
    int mv = pre[BTN - 1];
    if (m) g_idx[pre[tid] - 1] = tid;
    if (tid >= mv) g_idx[tid] = 0;
    if (tid == 0) g_cnt[0] = mv * 4;
}

// ---------------------------------------------------------------------------
__global__ void zero_fill_kernel(const int* __restrict__ mask,
                                 float* __restrict__ q,
                                 float* __restrict__ obeta,
                                 float* __restrict__ ok)
{
    int bt = blockIdx.x;
    if (mask[bt] != 0) return;
    int tid = threadIdx.x;
    float4* dst = (float4*)(q + (size_t)bt * 4 * VV);
#pragma unroll 4
    for (int i = tid; i < 32000; i += 256) dst[i] = make_float4(0.f, 0.f, 0.f, 0.f);
    if (tid < 4) {
        obeta[bt * 4 + tid] = 0.f;
        ok[bt * 4 + tid]    = 0.f;
    }
}

// ---------------------------------------------------------------------------
__global__ void w2b_kernel(const float* __restrict__ W2, const float* __restrict__ Wb,
                           const float* __restrict__ b2, const float* __restrict__ bb)
{
    if (blockIdx.x == DH / 8) {
        __shared__ float red[256];
        int tid = threadIdx.x;
        float s = 0.f;
        for (int i = tid; i < DM; i += 256) s += b2[i] * Wb[i];
        red[tid] = s; __syncthreads();
        for (int o = 128; o > 0; o >>= 1) { if (tid < o) red[tid] += red[tid + o]; __syncthreads(); }
        if (tid == 0) g_w2b[DH] = red[0] + bb[0];
        return;
    }
    int w = threadIdx.x >> 5, lane = threadIdx.x & 31;
    int j = blockIdx.x * 8 + w;
    const float* row = W2 + (size_t)j * DM;
    float s = 0.f;
    for (int i = lane; i < DM; i += 32) s += row[i] * Wb[i];
#pragma unroll
    for (int o = 16; o > 0; o >>= 1) s += __shfl_xor_sync(0xffffffffu, s, o);
    if (lane == 0) g_w2b[j] = s;
}

// ---------------------------------------------------------------------------
__global__ void packw_kernel(const float* __restrict__ W,
                             __half2* __restrict__ Dh, __half2* __restrict__ Dl,
                             int N)
{
    int n  = blockIdx.x * 256 + threadIdx.x;
    int k2 = blockIdx.y;
    float x0 = W[(size_t)(2 * k2    ) * N + n];
    float x1 = W[(size_t)(2 * k2 + 1) * N + n];
    __half h0 = __float2half_rn(x0), h1 = __float2half_rn(x1);
    Dh[(size_t)k2 * N + n] = __halves2half2(h0, h1);
    if (Dl)
        Dl[(size_t)k2 * N + n] = __halves2half2(
            __float2half_rn(x0 - __half2float(h0)),
            __float2half_rn(x1 - __half2float(h1)));
}

// ---------------------------------------------------------------------------
__global__ void s_kernel(const float* __restrict__ H, const int* __restrict__ ids,
                         const float* __restrict__ emb, const float* __restrict__ demb,
                         const float* __restrict__ lng, const float* __restrict__ lnb)
{
    int rp = blockIdx.x;
    if (rp >= g_cnt[0]) return;
    int bt  = g_idx[rp >> 2];
    int d   = rp & 3;
    int tid = threadIdx.x;

    const float* hrow = H    + (size_t)bt * DM;
    const float* erow = emb  + (size_t)ids[bt] * DM;
    const float* drow = demb + (size_t)d * DM;

    float x[4];
    float s = 0.f;
#pragma unroll
    for (int j = 0; j < 4; j++) {
        int i = j * 256 + tid;
        x[j] = hrow[i] + erow[i] + drow[i];
        s += x[j];
    }
    __shared__ float red[256];
    red[tid] = s; __syncthreads();
    for (int o = 128; o > 0; o >>= 1) { if (tid < o) red[tid] += red[tid + o]; __syncthreads(); }
    float mu = red[0] * (1.0f / DM);
    __syncthreads();

    float v = 0.f;
#pragma unroll
    for (int j = 0; j < 4; j++) { float dx = x[j] - mu; v += dx * dx; }
    red[tid] = v; __syncthreads();
    for (int o = 128; o > 0; o >>= 1) { if (tid < o) red[tid] += red[tid + o]; __syncthreads(); }
    float inv = rsqrtf(red[0] * (1.0f / DM) + 1e-5f);

#pragma unroll
    for (int j = 0; j < 4; j++) {
        int i = j * 256 + tid;
        float val = (x[j] - mu) * inv * lng[i] + lnb[i];
        __half h  = __float2half_rn(val);
        g_Shi[(size_t)rp * DM + i] = h;
        g_Slo[(size_t)rp * DM + i] = __float2half_rn(val - __half2float(h));
    }
}

// ---------------------------------------------------------------------------
#define KCH       32
#define ASTR2     20
#define BSTR2     136
#define A_TILE_H2 (128 * ASTR2)
#define B_TILE_H2 (16 * BSTR2)

// MODE 0: 2xFP16-split (3 HMMA), gelu -> g_G fp32 + g_Gh half.
// MODE 2: single pass, split-K raw partials.
// MODE 3: single pass (logits), scatter q + fused LSE partials.
template<int MODE>
__global__ void __launch_bounds__(256, 2)
mlp_h_kernel(const __half* __restrict__ Ah, const __half* __restrict__ Al,
             const __half2* __restrict__ Bh, const __half2* __restrict__ Bl,
             const float* __restrict__ bias,
             float* __restrict__ O1, __half* __restrict__ Oh,
             int N, int K)
{
    constexpr int NARR  = (MODE == 0) ? 2 : 1;
    constexpr int STG   = NARR * (A_TILE_H2 + B_TILE_H2);

    const int nv4     = g_cnt[0];
    const int rowBase = blockIdx.x * 128;
    if (rowBase >= nv4) return;
    extern __shared__ uint32_t smh[];
    const uint32_t su = smem_u32(smh);
    const int tid     = threadIdx.x;
    const int colBase = blockIdx.y * 128;

    int koff  = 0;
    int niter = K / KCH;
    if (MODE == 2) {
        koff  = blockIdx.z * (K / SPLITK);
        niter = K / SPLITK / KCH;
        O1   += (size_t)blockIdx.z * ROWS * DM;
    }

    const int lane = tid & 31, wid = tid >> 5;
    const int wr = wid >> 1, wc = wid & 1;
    const int g  = lane >> 2, tig = lane & 3;

    float acc[2][8][4];
#pragma unroll
    for (int mt = 0; mt < 2; mt++)
#pragma unroll
        for (int nt = 0; nt < 8; nt++)
#pragma unroll
            for (int k = 0; k < 4; k++) acc[mt][nt][k] = 0.f;

    const __half*  a0 = Ah + (size_t)rowBase * K + koff;
    const __half*  a1 = (NARR == 2) ? (Al + (size_t)rowBase * K + koff) : a0;
    const __half2* b0 = Bh + (size_t)(koff / 2) * N + colBase;
    const __half2* b1 = (NARR == 2) ? (Bl + (size_t)(koff / 2) * N + colBase) : b0;

    auto load_stage = [&](int s, int c) {
        const __half*  ap[2] = { a0, a1 };
        const __half2* bp[2] = { b0, b1 };
#pragma unroll
        for (int t = 0; t < NARR; t++) {
            uint32_t sa = su + (s * STG + t * A_TILE_H2) * 4;
            uint32_t sb = su + (s * STG + NARR * A_TILE_H2 + t * B_TILE_H2) * 4;
#pragma unroll
            for (int j = 0; j < 2; j++) {
                int idx = tid + 256 * j;
                int row = idx >> 2, seg = idx & 3;
                cp16(sa + (row * ASTR2 + seg * 4) * 4,
                     ap[t] + (size_t)row * K + c * KCH + seg * 8);
            }
#pragma unroll
            for (int j = 0; j < 2; j++) {
                int idx = tid + 256 * j;
                int k2r = idx >> 5, seg = idx & 31;
                cp16(sb + (k2r * BSTR2 + seg * 4) * 4,
                     bp[t] + (size_t)(c * 16 + k2r) * N + seg * 4);
            }
        }
    };

    load_stage(0, 0);
    CP_COMMIT();

    for (int it = 0; it < niter; it++) {
        int st = it & 1;
        CP_WAIT0();
        __syncthreads();
        if (it + 1 < niter) { load_stage(1 - st, it + 1); CP_COMMIT(); }

        const uint32_t* Ash = smh + st * STG;
        const uint32_t* Asl = Ash + A_TILE_H2;
        const uint32_t* Bsh = Ash + NARR * A_TILE_H2;
        const uint32_t* Bsl = Bsh + B_TILE_H2;

#pragma unroll
        for (int s = 0; s < 2; s++) {
            int s8 = s * 8;
            uint32_t ah[2][4], al[2][4];
#pragma unroll
            for (int mt = 0; mt < 2; mt++) {
                int m0 = wr * 32 + mt * 16;
                ah[mt][0] = Ash[(m0 + g    ) * ASTR2 + s8 + tig    ];
                ah[mt][1] = Ash[(m0 + g + 8) * ASTR2 + s8 + tig    ];
                ah[mt][2] = Ash[(m0 + g    ) * ASTR2 + s8 + tig + 4];
                ah[mt][3] = Ash[(m0 + g + 8) * ASTR2 + s8 + tig + 4];
                if (MODE == 0) {
                    al[mt][0] = Asl[(m0 + g    ) * ASTR2 + s8 + tig    ];
                    al[mt][1] = Asl[(m0 + g + 8) * ASTR2 + s8 + tig    ];
                    al[mt][2] = Asl[(m0 + g    ) * ASTR2 + s8 + tig + 4];
                    al[mt][3] = Asl[(m0 + g + 8) * ASTR2 + s8 + tig + 4];
                }
            }
            uint32_t bh[8][2], bl[8][2];
#pragma unroll
            for (int nt = 0; nt < 8; nt++) {
                int n0 = wc * 64 + nt * 8;
                bh[nt][0] = Bsh[(s8 + tig    ) * BSTR2 + n0 + g];
                bh[nt][1] = Bsh[(s8 + tig + 4) * BSTR2 + n0 + g];
                if (MODE == 0) {
                    bl[nt][0] = Bsl[(s8 + tig    ) * BSTR2 + n0 + g];
                    bl[nt][1] = Bsl[(s8 + tig + 4) * BSTR2 + n0 + g];
                }
            }
#pragma unroll
            for (int mt = 0; mt < 2; mt++)
#pragma unroll
                for (int nt = 0; nt < 8; nt++) {
                    mma_f16_16x8x16(acc[mt][nt], ah[mt], bh[nt]);
                    if (MODE == 0) {
                        mma_f16_16x8x16(acc[mt][nt], ah[mt], bl[nt]);
                        mma_f16_16x8x16(acc[mt][nt], al[mt], bh[nt]);
                    }
                }
        }
        __syncthreads();
    }

    // Epilogues
    if (MODE == 3) {
        float bqv[16];
#pragma unroll
        for (int nt = 0; nt < 8; nt++) {
            int c = colBase + wc * 64 + nt * 8 + tig * 2;
            bqv[nt * 2]     = bias[c];
            bqv[nt * 2 + 1] = bias[c + 1];
        }
#pragma unroll
        for (int mt = 0; mt < 2; mt++) {
            int rb  = rowBase + wr * 32 + mt * 16;
            int rc0 = rb + g, rc1 = rb + g + 8;
            bool ok0 = rc0 < nv4, ok1 = rc1 < nv4;
            int or0 = ok0 ? g_idx[rc0 >> 2] * 4 + (rc0 & 3) : 0;
            int or1 = ok1 ? g_idx[rc1 >> 2] * 4 + (rc1 & 3) : 0;
            float m0 = -1e30f, m1 = -1e30f;
#pragma unroll
            for (int nt = 0; nt < 8; nt++) {
                m0 = fmaxf(m0, fmaxf(acc[mt][nt][0] + bqv[nt*2],
                                     acc[mt][nt][1] + bqv[nt*2+1]));
                m1 = fmaxf(m1, fmaxf(acc[mt][nt][2] + bqv[nt*2],
                                     acc[mt][nt][3] + bqv[nt*2+1]));
            }
            float s0 = 0.f, s1 = 0.f;
#pragma unroll
            for (int nt = 0; nt < 8; nt++) {
                int c = colBase + wc * 64 + nt * 8 + tig * 2;
                float v00 = acc[mt][nt][0] + bqv[nt*2];
                float v01 = acc[mt][nt][1] + bqv[nt*2+1];
                float v10 = acc[mt][nt][2] + bqv[nt*2];
                float v11 = acc[mt][nt][3] + bqv[nt*2+1];
                s0 += expf(v00 - m0) + expf(v01 - m0);
                s1 += expf(v10 - m1) + expf(v11 - m1);
                if (ok0) *(float2*)&O1[(size_t)or0 * N + c] = make_float2(v00, v01);
                if (ok1) *(float2*)&O1[(size_t)or1 * N + c] = make_float2(v10, v11);
            }
#pragma unroll
            for (int off = 1; off <= 2; off <<= 1) {
                float mo = __shfl_xor_sync(0xffffffffu, m0, off);
                float so = __shfl_xor_sync(0xffffffffu, s0, off);
                float mn = fmaxf(m0, mo);
                s0 = s0 * expf(m0 - mn) + so * expf(mo - mn);
                m0 = mn;
                mo = __shfl_xor_sync(0xffffffffu, m1, off);
                so = __shfl_xor_sync(0xffffffffu, s1, off);
                mn = fmaxf(m1, mo);
                s1 = s1 * expf(m1 - mn) + so * expf(mo - mn);
                m1 = mn;
            }
            if (tig == 0) {
                int ct = blockIdx.y * 2 + wc;
                if (ok0) g_lse[(size_t)or0 * LSEC + ct] = make_float2(m0, s0);
                if (ok1) g_lse[(size_t)or1 * LSEC + ct] = make_float2(m1, s1);
            }
        }
    } else {
#pragma unroll
        for (int mt = 0; mt < 2; mt++) {
            int rb  = rowBase + wr * 32 + mt * 16;
            int rc0 = rb + g, rc1 = rb + g + 8;
#pragma unroll
            for (int nt = 0; nt < 8; nt++) {
                int c = colBase + wc * 64 + nt * 8 + tig * 2;
                if (MODE == 2) {
                    *(float2*)&O1[(size_t)rc0 * N + c] =
                        make_float2(acc[mt][nt][0], acc[mt][nt][1]);
                    *(float2*)&O1[(size_t)rc1 * N + c] =
                        make_float2(acc[mt][nt][2], acc[mt][nt][3]);
                } else {  // MODE 0
                    float b0 = bias[c], b1v = bias[c + 1];
                    float v00 = acc[mt][nt][0] + b0, v01 = acc[mt][nt][1] + b1v;
                    float v10 = acc[mt][nt][2] + b0, v11 = acc[mt][nt][3] + b1v;
                    v00 = 0.5f * v00 * (1.0f + erff(v00 * 0.70710678118654752f));
                    v01 = 0.5f * v01 * (1.0f + erff(v01 * 0.70710678118654752f));
                    v10 = 0.5f * v10 * (1.0f + erff(v10 * 0.70710678118654752f));
                    v11 = 0.5f * v11 * (1.0f + erff(v11 * 0.70710678118654752f));
                    *(float2*)&O1[(size_t)rc0 * N + c] = make_float2(v00, v01);
                    *(float2*)&O1[(size_t)rc1 * N + c] = make_float2(v10, v11);
                    *(__half2*)&Oh[(size_t)rc0 * N + c] = __floats2half2_rn(v00, v01);
                    *(__half2*)&Oh[(size_t)rc1 * N + c] = __floats2half2_rn(v10, v11);
                }
            }
        }
    }
}

// ---------------------------------------------------------------------------
__global__ void reduce_s2h_kernel(const float* __restrict__ b2)
{
    int i4 = blockIdx.x * 256 + threadIdx.x;
    int row = i4 >> 8;
    if (row >= g_cnt[0]) return;
    size_t i = (size_t)i4 * 4;
    const float4 p0 = *(const float4*)&g_P[i];
    const float4 p1 = *(const float4*)&g_P[(size_t)ROWS * DM + i];
    const float4 p2 = *(const float4*)&g_P[2 * (size_t)ROWS * DM + i];
    const float4 p3 = *(const float4*)&g_P[3 * (size_t)ROWS * DM + i];
    int c = (i4 & 255) * 4;
    float4 bv = *(const float4*)&b2[c];
    float vx = ((p0.x + p1.x) + (p2.x + p3.x)) + bv.x;
    float vy = ((p0.y + p1.y) + (p2.y + p3.y)) + bv.y;
    float vz = ((p0.z + p1.z) + (p2.z + p3.z)) + bv.z;
    float vw = ((p0.w + p1.w) + (p2.w + p3.w)) + bv.w;
    __half2* dst = (__half2*)&g_S2h[i];
    dst[0] = __floats2half2_rn(vx, vy);
    dst[1] = __floats2half2_rn(vz, vw);
}

// ---------------------------------------------------------------------------
__global__ void beta_kernel(float* __restrict__ obeta, float* __restrict__ ok)
{
    int rp = blockIdx.x;
    if (rp >= g_cnt[0]) return;
    int tid = threadIdx.x;
    const float* row = g_G + (size_t)rp * DH;
    float s = 0.f;
    for (int i = tid; i < DH; i += 256) s += row[i] * g_w2b[i];
    __shared__ float red[256];
    red[tid] = s; __syncthreads();
    for (int o = 128; o > 0; o >>= 1) { if (tid < o) red[tid] += red[tid + o]; __syncthreads(); }
    if (tid == 0) {
        float be = red[0] + g_w2b[DH];
        int orow = g_idx[rp >> 2] * 4 + (rp & 3);
        obeta[orow]  = be;
        g_beta[orow] = be;
        float sig = 1.f / (1.f + expf(-be));
        int k = (int)ceilf(sig * 8.f);
        k = max(1, min(8, k));
        if (sig < 0.25f) k = 0;
        ok[orow] = (float)k;
    }
}

// ---------------------------------------------------------------------------
// Final NLL from fused LSE partials + single target-logit read per row
__global__ void nll_final_kernel(const float* __restrict__ q,
                                 const int* __restrict__ mask,
                                 const int* __restrict__ labels)
{
    int r  = blockIdx.x;
    int d  = r & 3;
    int bt = r >> 2;
    int t  = bt % TT;
    int b  = bt / TT;
    int td = t + d + 1;
    bool valid = (td < TT) && (mask[bt] != 0) && (mask[b * TT + td] != 0);
    if (!valid) return;

    int tid = threadIdx.x;   // 256
    float m = -1e30f, s = 0.f;
    for (int i = tid; i < LSEC; i += 256) {
        float2 p = g_lse[(size_t)r * LSEC + i];
        float mn = fmaxf(m, p.x);
        s = s * expf(m - mn) + p.y * expf(p.x - mn);
        m = mn;
    }
    __shared__ float rm[256], rs[256];
    rm[tid] = m; rs[tid] = s; __syncthreads();
    for (int o = 128; o > 0; o >>= 1) {
        if (tid < o) {
            float mo = rm[tid + o], so = rs[tid + o];
            float mn = fmaxf(rm[tid], mo);
            rs[tid] = rs[tid] * expf(rm[tid] - mn) + so * expf(mo - mn);
            rm[tid] = mn;
        }
        __syncthreads();
    }
    if (tid == 0) {
        int tgt  = labels[b * TT + td];
        float lse = rm[0] + logf(rs[0]);
        float nll = lse - q[(size_t)r * VV + tgt];
        atomicAdd(&g_acc[0], (double)nll);
        atomicAdd(&g_acc[1], 1.0);
    }
}

// ---------------------------------------------------------------------------
__global__ void bce_kernel(const int* __restrict__ mask)
{
    int idx = blockIdx.x * 256 + threadIdx.x;
    if (idx >= BTN) return;
    int t = idx % TT;
    int b = idx / TT;
    if (mask[idx] == 0) return;
    float bsum = 0.f;
    bool anyv = false;
#pragma unroll
    for (int d = 0; d < 4; d++) {
        int td = t + d + 1;
        bool valid = (td < TT) && (mask[b * TT + td] != 0);
        float be  = g_beta[idx * 4 + d];
        float bce = fmaxf(be, 0.f) + log1pf(expf(-fabsf(be))) - (valid ? be : 0.f);
        bsum += bce;
        anyv |= valid;
    }
    if (anyv) {
        atomicAdd(&g_acc[2], (double)bsum);
        atomicAdd(&g_acc[3], 1.0);
    }
}

// ---------------------------------------------------------------------------
__global__ void fin_kernel(float* __restrict__ oloss)
{
    double cnt = g_acc[1];
    double Lq  = (cnt > 0.0) ? g_acc[0] / cnt : 0.0;
    double den = g_acc[3]; if (den < 1.0) den = 1.0;
    double Lb  = g_acc[2] / den;
    oloss[0] = (float)(Lq + Lb);
}

// ---------------------------------------------------------------------------
extern "C" void kernel_launch(void* const* d_in, const int* in_sizes, int n_in,
                              void* d_out, int out_size)
{
    const float* H      = (const float*)d_in[0];
    const int*   ids    = (const int*)  d_in[1];
    const int*   mask   = (const int*)  d_in[2];
    const int*   labels = (const int*)  d_in[3];
    const float* emb    = (const float*)d_in[4];
    const float* demb   = (const float*)d_in[5];
    const float* ln_g   = (const float*)d_in[6];
    const float* ln_b   = (const float*)d_in[7];
    const float* W1     = (const float*)d_in[8];
    const float* b1     = (const float*)d_in[9];
    const float* W2     = (const float*)d_in[10];
    const float* b2     = (const float*)d_in[11];
    const float* Wq     = (const float*)d_in[12];
    const float* bq     = (const float*)d_in[13];
    const float* Wb     = (const float*)d_in[14];
    const float* bb     = (const float*)d_in[15];

    float* out   = (float*)d_out;
    float* q     = out;
    float* obeta = out + (size_t)ROWS * VV;
    float* ok    = obeta + ROWS;
    float* oloss = ok + ROWS;

    void *pShi, *pSlo, *pW1h, *pW1l, *pW2h, *pG, *pGh, *pP, *pS2h, *pWqh;
    cudaGetSymbolAddress(&pShi, g_Shi);
    cudaGetSymbolAddress(&pSlo, g_Slo);
    cudaGetSymbolAddress(&pW1h, g_W1h);
    cudaGetSymbolAddress(&pW1l, g_W1l);
    cudaGetSymbolAddress(&pW2h, g_W2h);
    cudaGetSymbolAddress(&pG,   g_G);
    cudaGetSymbolAddress(&pGh,  g_Gh);
    cudaGetSymbolAddress(&pP,   g_P);
    cudaGetSymbolAddress(&pS2h, g_S2h);
    cudaGetSymbolAddress(&pWqh, g_Wqh);

    const int SM0 = 2 * 2 * (A_TILE_H2 + B_TILE_H2) * 4;
    const int SM1 = 2 * 1 * (A_TILE_H2 + B_TILE_H2) * 4;
    static bool init = false;
    static cudaStream_t s_side;
    static cudaEvent_t ev_fork, ev_join;
    if (!init) {
        cudaFuncSetAttribute(mlp_h_kernel<0>,
                             cudaFuncAttributeMaxDynamicSharedMemorySize, SM0);
        cudaFuncSetAttribute(mlp_h_kernel<2>,
                             cudaFuncAttributeMaxDynamicSharedMemorySize, SM1);
        cudaFuncSetAttribute(mlp_h_kernel<3>,
                             cudaFuncAttributeMaxDynamicSharedMemorySize, SM1);
        cudaStreamCreateWithFlags(&s_side, cudaStreamNonBlocking);
        cudaEventCreateWithFlags(&ev_fork, cudaEventDisableTiming);
        cudaEventCreateWithFlags(&ev_join, cudaEventDisableTiming);
        init = true;
    }

    // Fork: independent prep work on side stream
    cudaEventRecord(ev_fork, 0);
    cudaStreamWaitEvent(s_side, ev_fork, 0);
    zero_fill_kernel<<<BTN, 256, 0, s_side>>>(mask, q, obeta, ok);
    packw_kernel<<<dim3(VV / 256, DM / 2), 256, 0, s_side>>>(
        Wq, (__half2*)pWqh, nullptr, VV);
    packw_kernel<<<dim3(DM / 256, DH / 2), 256, 0, s_side>>>(
        W2, (__half2*)pW2h, nullptr, DM);
    w2b_kernel<<<DH / 8 + 1, 256, 0, s_side>>>(W2, Wb, b2, bb);
    cudaEventRecord(ev_join, s_side);

    // Main critical path
    compact_kernel<<<1, BTN>>>(mask);
    packw_kernel<<<dim3(DH / 256, DM / 2), 256>>>(W1, (__half2*)pW1h, (__half2*)pW1l, DH);
    s_kernel<<<ROWS, 256>>>(H, ids, emb, demb, ln_g, ln_b);

    mlp_h_kernel<0><<<dim3(ROWS / 128, DH / 128), 256, SM0>>>(
        (const __half*)pShi, (const __half*)pSlo,
        (const __half2*)pW1h, (const __half2*)pW1l,
        b1, (float*)pG, (__half*)pGh, DH, DM);

    // Join side work (w2b -> beta; W2h -> mlp2; Wqh -> logits; zero_fill -> output)
    cudaStreamWaitEvent(0, ev_join, 0);

    beta_kernel<<<ROWS, 256>>>(obeta, ok);

    mlp_h_kernel<2><<<dim3(ROWS / 128, DM / 128, SPLITK), 256, SM1>>>(
        (const __half*)pGh, nullptr, (const __half2*)pW2h, nullptr,
        nullptr, (float*)pP, nullptr, DM, DH);

    reduce_s2h_kernel<<<ROWS * DM / 1024, 256>>>(b2);

    mlp_h_kernel<3><<<dim3(ROWS / 128, VV / 128), 256, SM1>>>(
        (const __half*)pS2h, nullptr, (const __half2*)pWqh, nullptr,
        bq, q, nullptr, VV, DM);

    nll_final_kernel<<<ROWS, 256>>>(q, mask, labels);
    bce_kernel<<<(BTN + 255) / 256, 256>>>(mask);
    fin_kernel<<<1, 1>>>(oloss);

    (void)in_sizes; (void)n_in; (void)out_size;
}

// round 11
// speedup vs baseline: 2.2192x; 1.0207x over previous
#include <cuda_runtime.h>
#include <cuda_fp16.h>
#include <math.h>
#include <stdint.h>

// Problem constants
#define BB   2
#define TT   512
#define DM   1024
#define DH   4096
#define DD   4
#define VV   32000
#define ROWS (BB*TT*DD)   // 4096
#define BTN  (BB*TT)      // 1024
#define SPLITK 4
#define LSEC  (2 * (VV / 128))   // 500 LSE partials per row

// Scratch (static device globals — no allocation allowed)
__device__ __half  g_Shi[ROWS*DM];
__device__ __half  g_Slo[ROWS*DM];
__device__ __half2 g_W1h[(DM/2)*DH];
__device__ __half2 g_W1l[(DM/2)*DH];
__device__ __half2 g_W2h[(DH/2)*DM];
__device__ float   g_G  [ROWS*DH];         // fp32-exact gelu (beta path)
__device__ __half  g_Gh [ROWS*DH];         // fp16 gelu (q path)
__device__ float   g_P  [SPLITK*ROWS*DM];
__device__ __half  g_S2h[ROWS*DM];
__device__ __half2 g_Wqh[(DM/2)*VV];
__device__ float   g_w2b[DH+1];
__device__ float   g_beta[ROWS];
__device__ float2  g_lse[(size_t)ROWS*LSEC];
__device__ int     g_idx [BTN];
__device__ int     g_cnt [1];
__device__ double  g_acc[4];

// ============================================================================
__device__ __forceinline__ uint32_t smem_u32(const void* p) {
    uint32_t a;
    asm("{ .reg .u64 t; cvta.to.shared.u64 t, %1; cvt.u32.u64 %0, t; }"
        : "=r"(a) : "l"(p));
    return a;
}
__device__ __forceinline__ void cp16(uint32_t s, const void* g) {
    asm volatile("cp.async.cg.shared.global [%0], [%1], 16;" :: "r"(s), "l"(g));
}
#define CP_COMMIT() asm volatile("cp.async.commit_group;" ::: "memory")
#define CP_WAIT0()  asm volatile("cp.async.wait_group 0;" ::: "memory")

__device__ __forceinline__ void mma_f16_16x8x16(float* d, const uint32_t* a,
                                                const uint32_t* b) {
    asm volatile(
        "mma.sync.aligned.m16n8k16.row.col.f32.f16.f16.f32 "
        "{%0,%1,%2,%3}, {%4,%5,%6,%7}, {%8,%9}, {%0,%1,%2,%3};"
        : "+f"(d[0]), "+f"(d[1]), "+f"(d[2]), "+f"(d[3])
        : "r"(a[0]), "r"(a[1]), "r"(a[2]), "r"(a[3]), "r"(b[0]), "r"(b[1]));
}

// ============================================================================
// compact + zero g_acc
__global__ void compact_kernel(const int* __restrict__ mask) {
    __shared__ int pre[BTN];
    int tid = threadIdx.x;
    if (tid < 4) g_acc[tid] = 0.0;
    int m = (mask[tid] != 0) ? 1 : 0;
    pre[tid] = m;
    __syncthreads();
    for (int o = 1; o < BTN; o <<= 1) {
        int v = (tid >= o) ? pre[tid - o] : 0;
        __syncthreads();
        pre[tid] += v;
        __syncthreads();
    }
    int mv = pre[BTN - 1];
    if (m) g_idx[pre[tid] - 1] = tid;
    if (tid >= mv) g_idx[tid] = 0;
    if (tid == 0) g_cnt[0] = mv * 4;
}

// ---------------------------------------------------------------------------
__global__ void zero_fill_kernel(const int* __restrict__ mask,
                                 float* __restrict__ q,
                                 float* __restrict__ obeta,
                                 float* __restrict__ ok)
{
    int bt = blockIdx.x;
    if (mask[bt] != 0) return;
    int tid = threadIdx.x;
    float4* dst = (float4*)(q + (size_t)bt * 4 * VV);
#pragma unroll 4
    for (int i = tid; i < 32000; i += 256) dst[i] = make_float4(0.f, 0.f, 0.f, 0.f);
    if (tid < 4) {
        obeta[bt * 4 + tid] = 0.f;
        ok[bt * 4 + tid]    = 0.f;
    }
}

// ---------------------------------------------------------------------------
__global__ void w2b_kernel(const float* __restrict__ W2, const float* __restrict__ Wb,
                           const float* __restrict__ b2, const float* __restrict__ bb)
{
    if (blockIdx.x == DH / 8) {
        __shared__ float red[256];
        int tid = threadIdx.x;
        float s = 0.f;
        for (int i = tid; i < DM; i += 256) s += b2[i] * Wb[i];
        red[tid] = s; __syncthreads();
        for (int o = 128; o > 0; o >>= 1) { if (tid < o) red[tid] += red[tid + o]; __syncthreads(); }
        if (tid == 0) g_w2b[DH] = red[0] + bb[0];
        return;
    }
    int w = threadIdx.x >> 5, lane = threadIdx.x & 31;
    int j = blockIdx.x * 8 + w;
    const float* row = W2 + (size_t)j * DM;
    float s = 0.f;
    for (int i = lane; i < DM; i += 32) s += row[i] * Wb[i];
#pragma unroll
    for (int o = 16; o > 0; o >>= 1) s += __shfl_xor_sync(0xffffffffu, s, o);
    if (lane == 0) g_w2b[j] = s;
}

// ---------------------------------------------------------------------------
__global__ void packw_kernel(const float* __restrict__ W,
                             __half2* __restrict__ Dh, __half2* __restrict__ Dl,
                             int N)
{
    int n  = blockIdx.x * 256 + threadIdx.x;
    int k2 = blockIdx.y;
    float x0 = W[(size_t)(2 * k2    ) * N + n];
    float x1 = W[(size_t)(2 * k2 + 1) * N + n];
    __half h0 = __float2half_rn(x0), h1 = __float2half_rn(x1);
    Dh[(size_t)k2 * N + n] = __halves2half2(h0, h1);
    if (Dl)
        Dl[(size_t)k2 * N + n] = __halves2half2(
            __float2half_rn(x0 - __half2float(h0)),
            __float2half_rn(x1 - __half2float(h1)));
}

// ---------------------------------------------------------------------------
__global__ void s_kernel(const float* __restrict__ H, const int* __restrict__ ids,
                         const float* __restrict__ emb, const float* __restrict__ demb,
                         const float* __restrict__ lng, const float* __restrict__ lnb)
{
    int rp = blockIdx.x;
    if (rp >= g_cnt[0]) return;
    int bt  = g_idx[rp >> 2];
    int d   = rp & 3;
    int tid = threadIdx.x;

    const float* hrow = H    + (size_t)bt * DM;
    const float* erow = emb  + (size_t)ids[bt] * DM;
    const float* drow = demb + (size_t)d * DM;

    float x[4];
    float s = 0.f;
#pragma unroll
    for (int j = 0; j < 4; j++) {
        int i = j * 256 + tid;
        x[j] = hrow[i] + erow[i] + drow[i];
        s += x[j];
    }
    __shared__ float red[256];
    red[tid] = s; __syncthreads();
    for (int o = 128; o > 0; o >>= 1) { if (tid < o) red[tid] += red[tid + o]; __syncthreads(); }
    float mu = red[0] * (1.0f / DM);
    __syncthreads();

    float v = 0.f;
#pragma unroll
    for (int j = 0; j < 4; j++) { float dx = x[j] - mu; v += dx * dx; }
    red[tid] = v; __syncthreads();
    for (int o = 128; o > 0; o >>= 1) { if (tid < o) red[tid] += red[tid + o]; __syncthreads(); }
    float inv = rsqrtf(red[0] * (1.0f / DM) + 1e-5f);

#pragma unroll
    for (int j = 0; j < 4; j++) {
        int i = j * 256 + tid;
        float val = (x[j] - mu) * inv * lng[i] + lnb[i];
        __half h  = __float2half_rn(val);
        g_Shi[(size_t)rp * DM + i] = h;
        g_Slo[(size_t)rp * DM + i] = __float2half_rn(val - __half2float(h));
    }
}

// ---------------------------------------------------------------------------
#define KCH       32
#define ASTR2     20
#define BSTR2     136
#define A_TILE_H2 (128 * ASTR2)
#define B_TILE_H2 (16 * BSTR2)

// MODE 0: 2xFP16-split (3 HMMA), gelu -> g_G fp32 + g_Gh half.
// MODE 2: single pass, split-K raw partials.
// MODE 3: single pass (logits), scatter q + fused LSE partials.
template<int MODE>
__global__ void __launch_bounds__(256, 2)
mlp_h_kernel(const __half* __restrict__ Ah, const __half* __restrict__ Al,
             const __half2* __restrict__ Bh, const __half2* __restrict__ Bl,
             const float* __restrict__ bias,
             float* __restrict__ O1, __half* __restrict__ Oh,
             int N, int K)
{
    constexpr int NARR  = (MODE == 0) ? 2 : 1;
    constexpr int STG   = NARR * (A_TILE_H2 + B_TILE_H2);

    const int nv4     = g_cnt[0];
    const int rowBase = blockIdx.x * 128;
    if (rowBase >= nv4) return;
    extern __shared__ uint32_t smh[];
    const uint32_t su = smem_u32(smh);
    const int tid     = threadIdx.x;
    const int colBase = blockIdx.y * 128;

    int koff  = 0;
    int niter = K / KCH;
    if (MODE == 2) {
        koff  = blockIdx.z * (K / SPLITK);
        niter = K / SPLITK / KCH;
        O1   += (size_t)blockIdx.z * ROWS * DM;
    }

    const int lane = tid & 31, wid = tid >> 5;
    const int wr = wid >> 1, wc = wid & 1;
    const int g  = lane >> 2, tig = lane & 3;

    float acc[2][8][4];
#pragma unroll
    for (int mt = 0; mt < 2; mt++)
#pragma unroll
        for (int nt = 0; nt < 8; nt++)
#pragma unroll
            for (int k = 0; k < 4; k++) acc[mt][nt][k] = 0.f;

    const __half*  a0 = Ah + (size_t)rowBase * K + koff;
    const __half*  a1 = (NARR == 2) ? (Al + (size_t)rowBase * K + koff) : a0;
    const __half2* b0 = Bh + (size_t)(koff / 2) * N + colBase;
    const __half2* b1 = (NARR == 2) ? (Bl + (size_t)(koff / 2) * N + colBase) : b0;

    auto load_stage = [&](int s, int c) {
        const __half*  ap[2] = { a0, a1 };
        const __half2* bp[2] = { b0, b1 };
#pragma unroll
        for (int t = 0; t < NARR; t++) {
            uint32_t sa = su + (s * STG + t * A_TILE_H2) * 4;
            uint32_t sb = su + (s * STG + NARR * A_TILE_H2 + t * B_TILE_H2) * 4;
#pragma unroll
            for (int j = 0; j < 2; j++) {
                int idx = tid + 256 * j;
                int row = idx >> 2, seg = idx & 3;
                cp16(sa + (row * ASTR2 + seg * 4) * 4,
                     ap[t] + (size_t)row * K + c * KCH + seg * 8);
            }
#pragma unroll
            for (int j = 0; j < 2; j++) {
                int idx = tid + 256 * j;
                int k2r = idx >> 5, seg = idx & 31;
                cp16(sb + (k2r * BSTR2 + seg * 4) * 4,
                     bp[t] + (size_t)(c * 16 + k2r) * N + seg * 4);
            }
        }
    };

    load_stage(0, 0);
    CP_COMMIT();

    for (int it = 0; it < niter; it++) {
        int st = it & 1;
        CP_WAIT0();
        __syncthreads();
        if (it + 1 < niter) { load_stage(1 - st, it + 1); CP_COMMIT(); }

        const uint32_t* Ash = smh + st * STG;
        const uint32_t* Asl = Ash + A_TILE_H2;
        const uint32_t* Bsh = Ash + NARR * A_TILE_H2;
        const uint32_t* Bsl = Bsh + B_TILE_H2;

#pragma unroll
        for (int s = 0; s < 2; s++) {
            int s8 = s * 8;
            uint32_t ah[2][4], al[2][4];
#pragma unroll
            for (int mt = 0; mt < 2; mt++) {
                int m0 = wr * 32 + mt * 16;
                ah[mt][0] = Ash[(m0 + g    ) * ASTR2 + s8 + tig    ];
                ah[mt][1] = Ash[(m0 + g + 8) * ASTR2 + s8 + tig    ];
                ah[mt][2] = Ash[(m0 + g    ) * ASTR2 + s8 + tig + 4];
                ah[mt][3] = Ash[(m0 + g + 8) * ASTR2 + s8 + tig + 4];
                if (MODE == 0) {
                    al[mt][0] = Asl[(m0 + g    ) * ASTR2 + s8 + tig    ];
                    al[mt][1] = Asl[(m0 + g + 8) * ASTR2 + s8 + tig    ];
                    al[mt][2] = Asl[(m0 + g    ) * ASTR2 + s8 + tig + 4];
                    al[mt][3] = Asl[(m0 + g + 8) * ASTR2 + s8 + tig + 4];
                }
            }
            uint32_t bh[8][2], bl[8][2];
#pragma unroll
            for (int nt = 0; nt < 8; nt++) {
                int n0 = wc * 64 + nt * 8;
                bh[nt][0] = Bsh[(s8 + tig    ) * BSTR2 + n0 + g];
                bh[nt][1] = Bsh[(s8 + tig + 4) * BSTR2 + n0 + g];
                if (MODE == 0) {
                    bl[nt][0] = Bsl[(s8 + tig    ) * BSTR2 + n0 + g];
                    bl[nt][1] = Bsl[(s8 + tig + 4) * BSTR2 + n0 + g];
                }
            }
#pragma unroll
            for (int mt = 0; mt < 2; mt++)
#pragma unroll
                for (int nt = 0; nt < 8; nt++) {
                    mma_f16_16x8x16(acc[mt][nt], ah[mt], bh[nt]);
                    if (MODE == 0) {
                        mma_f16_16x8x16(acc[mt][nt], ah[mt], bl[nt]);
                        mma_f16_16x8x16(acc[mt][nt], al[mt], bh[nt]);
                    }
                }
        }
        __syncthreads();
    }

    // Epilogues
    if (MODE == 3) {
        float bqv[16];
#pragma unroll
        for (int nt = 0; nt < 8; nt++) {
            int c = colBase + wc * 64 + nt * 8 + tig * 2;
            bqv[nt * 2]     = bias[c];
            bqv[nt * 2 + 1] = bias[c + 1];
        }
#pragma unroll
        for (int mt = 0; mt < 2; mt++) {
            int rb  = rowBase + wr * 32 + mt * 16;
            int rc0 = rb + g, rc1 = rb + g + 8;
            bool ok0 = rc0 < nv4, ok1 = rc1 < nv4;
            int or0 = ok0 ? g_idx[rc0 >> 2] * 4 + (rc0 & 3) : 0;
            int or1 = ok1 ? g_idx[rc1 >> 2] * 4 + (rc1 & 3) : 0;
            float m0 = -1e30f, m1 = -1e30f;
#pragma unroll
            for (int nt = 0; nt < 8; nt++) {
                m0 = fmaxf(m0, fmaxf(acc[mt][nt][0] + bqv[nt*2],
                                     acc[mt][nt][1] + bqv[nt*2+1]));
                m1 = fmaxf(m1, fmaxf(acc[mt][nt][2] + bqv[nt*2],
                                     acc[mt][nt][3] + bqv[nt*2+1]));
            }
            float s0 = 0.f, s1 = 0.f;
#pragma unroll
            for (int nt = 0; nt < 8; nt++) {
                int c = colBase + wc * 64 + nt * 8 + tig * 2;
                float v00 = acc[mt][nt][0] + bqv[nt*2];
                float v01 = acc[mt][nt][1] + bqv[nt*2+1];
                float v10 = acc[mt][nt][2] + bqv[nt*2];
                float v11 = acc[mt][nt][3] + bqv[nt*2+1];
                s0 += expf(v00 - m0) + expf(v01 - m0);
                s1 += expf(v10 - m1) + expf(v11 - m1);
                if (ok0) *(float2*)&O1[(size_t)or0 * N + c] = make_float2(v00, v01);
                if (ok1) *(float2*)&O1[(size_t)or1 * N + c] = make_float2(v10, v11);
            }
#pragma unroll
            for (int off = 1; off <= 2; off <<= 1) {
                float mo = __shfl_xor_sync(0xffffffffu, m0, off);
                float so = __shfl_xor_sync(0xffffffffu, s0, off);
                float mn = fmaxf(m0, mo);
                s0 = s0 * expf(m0 - mn) + so * expf(mo - mn);
                m0 = mn;
                mo = __shfl_xor_sync(0xffffffffu, m1, off);
                so = __shfl_xor_sync(0xffffffffu, s1, off);
                mn = fmaxf(m1, mo);
                s1 = s1 * expf(m1 - mn) + so * expf(mo - mn);
                m1 = mn;
            }
            if (tig == 0) {
                int ct = blockIdx.y * 2 + wc;
                if (ok0) g_lse[(size_t)or0 * LSEC + ct] = make_float2(m0, s0);
                if (ok1) g_lse[(size_t)or1 * LSEC + ct] = make_float2(m1, s1);
            }
        }
    } else {
#pragma unroll
        for (int mt = 0; mt < 2; mt++) {
            int rb  = rowBase + wr * 32 + mt * 16;
            int rc0 = rb + g, rc1 = rb + g + 8;
#pragma unroll
            for (int nt = 0; nt < 8; nt++) {
                int c = colBase + wc * 64 + nt * 8 + tig * 2;
                if (MODE == 2) {
                    *(float2*)&O1[(size_t)rc0 * N + c] =
                        make_float2(acc[mt][nt][0], acc[mt][nt][1]);
                    *(float2*)&O1[(size_t)rc1 * N + c] =
                        make_float2(acc[mt][nt][2], acc[mt][nt][3]);
                } else {  // MODE 0
                    float b0 = bias[c], b1v = bias[c + 1];
                    float v00 = acc[mt][nt][0] + b0, v01 = acc[mt][nt][1] + b1v;
                    float v10 = acc[mt][nt][2] + b0, v11 = acc[mt][nt][3] + b1v;
                    v00 = 0.5f * v00 * (1.0f + erff(v00 * 0.70710678118654752f));
                    v01 = 0.5f * v01 * (1.0f + erff(v01 * 0.70710678118654752f));
                    v10 = 0.5f * v10 * (1.0f + erff(v10 * 0.70710678118654752f));
                    v11 = 0.5f * v11 * (1.0f + erff(v11 * 0.70710678118654752f));
                    *(float2*)&O1[(size_t)rc0 * N + c] = make_float2(v00, v01);
                    *(float2*)&O1[(size_t)rc1 * N + c] = make_float2(v10, v11);
                    *(__half2*)&Oh[(size_t)rc0 * N + c] = __floats2half2_rn(v00, v01);
                    *(__half2*)&Oh[(size_t)rc1 * N + c] = __floats2half2_rn(v10, v11);
                }
            }
        }
    }
}

// ---------------------------------------------------------------------------
__global__ void reduce_s2h_kernel(const float* __restrict__ b2)
{
    int i4 = blockIdx.x * 256 + threadIdx.x;
    int row = i4 >> 8;
    if (row >= g_cnt[0]) return;
    size_t i = (size_t)i4 * 4;
    const float4 p0 = *(const float4*)&g_P[i];
    const float4 p1 = *(const float4*)&g_P[(size_t)ROWS * DM + i];
    const float4 p2 = *(const float4*)&g_P[2 * (size_t)ROWS * DM + i];
    const float4 p3 = *(const float4*)&g_P[3 * (size_t)ROWS * DM + i];
    int c = (i4 & 255) * 4;
    float4 bv = *(const float4*)&b2[c];
    float vx = ((p0.x + p1.x) + (p2.x + p3.x)) + bv.x;
    float vy = ((p0.y + p1.y) + (p2.y + p3.y)) + bv.y;
    float vz = ((p0.z + p1.z) + (p2.z + p3.z)) + bv.z;
    float vw = ((p0.w + p1.w) + (p2.w + p3.w)) + bv.w;
    __half2* dst = (__half2*)&g_S2h[i];
    dst[0] = __floats2half2_rn(vx, vy);
    dst[1] = __floats2half2_rn(vz, vw);
}

// ---------------------------------------------------------------------------
__global__ void beta_kernel(float* __restrict__ obeta, float* __restrict__ ok)
{
    int rp = blockIdx.x;
    if (rp >= g_cnt[0]) return;
    int tid = threadIdx.x;
    const float* row = g_G + (size_t)rp * DH;
    float s = 0.f;
    for (int i = tid; i < DH; i += 256) s += row[i] * g_w2b[i];
    __shared__ float red[256];
    red[tid] = s; __syncthreads();
    for (int o = 128; o > 0; o >>= 1) { if (tid < o) red[tid] += red[tid + o]; __syncthreads(); }
    if (tid == 0) {
        float be = red[0] + g_w2b[DH];
        int orow = g_idx[rp >> 2] * 4 + (rp & 3);
        obeta[orow]  = be;
        g_beta[orow] = be;
        float sig = 1.f / (1.f + expf(-be));
        int k = (int)ceilf(sig * 8.f);
        k = max(1, min(8, k));
        if (sig < 0.25f) k = 0;
        ok[orow] = (float)k;
    }
}

// ---------------------------------------------------------------------------
__global__ void nll_final_kernel(const float* __restrict__ q,
                                 const int* __restrict__ mask,
                                 const int* __restrict__ labels)
{
    int r  = blockIdx.x;
    int d  = r & 3;
    int bt = r >> 2;
    int t  = bt % TT;
    int b  = bt / TT;
    int td = t + d + 1;
    bool valid = (td < TT) && (mask[bt] != 0) && (mask[b * TT + td] != 0);
    if (!valid) return;

    int tid = threadIdx.x;
    float m = -1e30f, s = 0.f;
    for (int i = tid; i < LSEC; i += 256) {
        float2 p = g_lse[(size_t)r * LSEC + i];
        float mn = fmaxf(m, p.x);
        s = s * expf(m - mn) + p.y * expf(p.x - mn);
        m = mn;
    }
    __shared__ float rm[256], rs[256];
    rm[tid] = m; rs[tid] = s; __syncthreads();
    for (int o = 128; o > 0; o >>= 1) {
        if (tid < o) {
            float mo = rm[tid + o], so = rs[tid + o];
            float mn = fmaxf(rm[tid], mo);
            rs[tid] = rs[tid] * expf(rm[tid] - mn) + so * expf(mo - mn);
            rm[tid] = mn;
        }
        __syncthreads();
    }
    if (tid == 0) {
        int tgt  = labels[b * TT + td];
        float lse = rm[0] + logf(rs[0]);
        float nll = lse - q[(size_t)r * VV + tgt];
        atomicAdd(&g_acc[0], (double)nll);
        atomicAdd(&g_acc[1], 1.0);
    }
}

// ---------------------------------------------------------------------------
__global__ void bce_kernel(const int* __restrict__ mask)
{
    int idx = blockIdx.x * 256 + threadIdx.x;
    if (idx >= BTN) return;
    int t = idx % TT;
    int b = idx / TT;
    if (mask[idx] == 0) return;
    float bsum = 0.f;
    bool anyv = false;
#pragma unroll
    for (int d = 0; d < 4; d++) {
        int td = t + d + 1;
        bool valid = (td < TT) && (mask[b * TT + td] != 0);
        float be  = g_beta[idx * 4 + d];
        float bce = fmaxf(be, 0.f) + log1pf(expf(-fabsf(be))) - (valid ? be : 0.f);
        bsum += bce;
        anyv |= valid;
    }
    if (anyv) {
        atomicAdd(&g_acc[2], (double)bsum);
        atomicAdd(&g_acc[3], 1.0);
    }
}

// ---------------------------------------------------------------------------
__global__ void fin_kernel(float* __restrict__ oloss)
{
    double cnt = g_acc[1];
    double Lq  = (cnt > 0.0) ? g_acc[0] / cnt : 0.0;
    double den = g_acc[3]; if (den < 1.0) den = 1.0;
    double Lb  = g_acc[2] / den;
    oloss[0] = (float)(Lq + Lb);
}

// ---------------------------------------------------------------------------
extern "C" void kernel_launch(void* const* d_in, const int* in_sizes, int n_in,
                              void* d_out, int out_size)
{
    const float* H      = (const float*)d_in[0];
    const int*   ids    = (const int*)  d_in[1];
    const int*   mask   = (const int*)  d_in[2];
    const int*   labels = (const int*)  d_in[3];
    const float* emb    = (const float*)d_in[4];
    const float* demb   = (const float*)d_in[5];
    const float* ln_g   = (const float*)d_in[6];
    const float* ln_b   = (const float*)d_in[7];
    const float* W1     = (const float*)d_in[8];
    const float* b1     = (const float*)d_in[9];
    const float* W2     = (const float*)d_in[10];
    const float* b2     = (const float*)d_in[11];
    const float* Wq     = (const float*)d_in[12];
    const float* bq     = (const float*)d_in[13];
    const float* Wb     = (const float*)d_in[14];
    const float* bb     = (const float*)d_in[15];

    float* out   = (float*)d_out;
    float* q     = out;
    float* obeta = out + (size_t)ROWS * VV;
    float* ok    = obeta + ROWS;
    float* oloss = ok + ROWS;

    void *pShi, *pSlo, *pW1h, *pW1l, *pW2h, *pG, *pGh, *pP, *pS2h, *pWqh;
    cudaGetSymbolAddress(&pShi, g_Shi);
    cudaGetSymbolAddress(&pSlo, g_Slo);
    cudaGetSymbolAddress(&pW1h, g_W1h);
    cudaGetSymbolAddress(&pW1l, g_W1l);
    cudaGetSymbolAddress(&pW2h, g_W2h);
    cudaGetSymbolAddress(&pG,   g_G);
    cudaGetSymbolAddress(&pGh,  g_Gh);
    cudaGetSymbolAddress(&pP,   g_P);
    cudaGetSymbolAddress(&pS2h, g_S2h);
    cudaGetSymbolAddress(&pWqh, g_Wqh);

    const int SM0 = 2 * 2 * (A_TILE_H2 + B_TILE_H2) * 4;
    const int SM1 = 2 * 1 * (A_TILE_H2 + B_TILE_H2) * 4;
    static bool init = false;
    static cudaStream_t s_prep, s_beta;
    static cudaEvent_t ev_fork, ev_prep, ev_g, ev_beta;
    if (!init) {
        cudaFuncSetAttribute(mlp_h_kernel<0>,
                             cudaFuncAttributeMaxDynamicSharedMemorySize, SM0);
        cudaFuncSetAttribute(mlp_h_kernel<2>,
                             cudaFuncAttributeMaxDynamicSharedMemorySize, SM1);
        cudaFuncSetAttribute(mlp_h_kernel<3>,
                             cudaFuncAttributeMaxDynamicSharedMemorySize, SM1);
        cudaStreamCreateWithFlags(&s_prep, cudaStreamNonBlocking);
        cudaStreamCreateWithFlags(&s_beta, cudaStreamNonBlocking);
        cudaEventCreateWithFlags(&ev_fork, cudaEventDisableTiming);
        cudaEventCreateWithFlags(&ev_prep, cudaEventDisableTiming);
        cudaEventCreateWithFlags(&ev_g,    cudaEventDisableTiming);
        cudaEventCreateWithFlags(&ev_beta, cudaEventDisableTiming);
        init = true;
    }

    // Fork: independent prep on s_prep
    cudaEventRecord(ev_fork, 0);
    cudaStreamWaitEvent(s_prep, ev_fork, 0);
    zero_fill_kernel<<<BTN, 256, 0, s_prep>>>(mask, q, obeta, ok);
    packw_kernel<<<dim3(VV / 256, DM / 2), 256, 0, s_prep>>>(
        Wq, (__half2*)pWqh, nullptr, VV);
    packw_kernel<<<dim3(DM / 256, DH / 2), 256, 0, s_prep>>>(
        W2, (__half2*)pW2h, nullptr, DM);
    w2b_kernel<<<DH / 8 + 1, 256, 0, s_prep>>>(W2, Wb, b2, bb);
    cudaEventRecord(ev_prep, s_prep);

    // Main critical path
    compact_kernel<<<1, BTN>>>(mask);
    packw_kernel<<<dim3(DH / 256, DM / 2), 256>>>(W1, (__half2*)pW1h, (__half2*)pW1l, DH);
    s_kernel<<<ROWS, 256>>>(H, ids, emb, demb, ln_g, ln_b);

    mlp_h_kernel<0><<<dim3(ROWS / 128, DH / 128), 256, SM0>>>(
        (const __half*)pShi, (const __half*)pSlo,
        (const __half2*)pW1h, (const __half2*)pW1l,
        b1, (float*)pG, (__half*)pGh, DH, DM);
    cudaEventRecord(ev_g, 0);

    // Side: beta + bce overlap with mlp2/reduce/logits
    cudaStreamWaitEvent(s_beta, ev_g, 0);          // G ready (and compact done)
    cudaStreamWaitEvent(s_beta, ev_prep, 0);       // w2b ready
    beta_kernel<<<ROWS, 256, 0, s_beta>>>(obeta, ok);
    bce_kernel<<<(BTN + 255) / 256, 256, 0, s_beta>>>(mask);
    cudaEventRecord(ev_beta, s_beta);

    // Main: needs W2h/Wqh from prep
    cudaStreamWaitEvent(0, ev_prep, 0);

    mlp_h_kernel<2><<<dim3(ROWS / 128, DM / 128, SPLITK), 256, SM1>>>(
        (const __half*)pGh, nullptr, (const __half2*)pW2h, nullptr,
        nullptr, (float*)pP, nullptr, DM, DH);

    reduce_s2h_kernel<<<ROWS * DM / 1024, 256>>>(b2);

    mlp_h_kernel<3><<<dim3(ROWS / 128, VV / 128), 256, SM1>>>(
        (const __half*)pS2h, nullptr, (const __half2*)pWqh, nullptr,
        bq, q, nullptr, VV, DM);

    nll_final_kernel<<<ROWS, 256>>>(q, mask, labels);

    cudaStreamWaitEvent(0, ev_beta, 0);
    fin_kernel<<<1, 1>>>(oloss);

    (void)in_sizes; (void)n_in; (void)out_size;
}